// round 13
// baseline (speedup 1.0000x reference)
#include <cuda_runtime.h>
#include <cuda_fp16.h>
#include <cstdint>

#define N_NODES 100000
#define N_EDGES 1600000
#define D 128
#define SCAN_B 256

// Scratch (allocation-free: __device__ globals)
__device__ int    g_cnt[N_NODES];
__device__ int    g_rowstart[N_NODES + 1];
__device__ int    g_bsum[1024];
__device__ int    g_locoff[N_EDGES];
__device__ int    g_csrsrc[N_EDGES];
__device__ float  g_wfs[D * 2];
__device__ float  g_wfn[D * 2];
__device__ float  g_bf[2];
__device__ __align__(16) float g_z[(size_t)N_NODES * 4];  // [self0,self1,neigh0,neigh1]
__device__ __align__(128) __half g_feat16[(size_t)N_NODES * D];
__device__ __align__(128) __half g_agg16[(size_t)N_NODES * D];
__device__ __align__(128) __half g_w16[2][D * D];  // W1s^T, W1n^T (n-major)

// ---------------------------------------------------------------- helpers
__device__ __forceinline__ void mma_f16(float* d, const uint32_t* a, const uint32_t* b) {
    asm volatile(
        "mma.sync.aligned.m16n8k16.row.col.f32.f16.f16.f32 "
        "{%0,%1,%2,%3}, {%4,%5,%6,%7}, {%8,%9}, {%0,%1,%2,%3};"
        : "+f"(d[0]), "+f"(d[1]), "+f"(d[2]), "+f"(d[3])
        : "r"(a[0]), "r"(a[1]), "r"(a[2]), "r"(a[3]), "r"(b[0]), "r"(b[1]));
}
__device__ __forceinline__ void cp16(uint32_t dst, const void* src) {
    asm volatile("cp.async.cg.shared.global [%0], [%1], 16;" :: "r"(dst), "l"(src));
}
#define CP_COMMIT() asm volatile("cp.async.commit_group;" ::: "memory")
#define CP_WAIT(n)  asm volatile("cp.async.wait_group %0;" :: "n"(n) : "memory")

// ---------------------------------------------------------------- conversions
__global__ void conv16_kernel(const float* __restrict__ in, __half* __restrict__ out, int n4) {
    int i = blockIdx.x * blockDim.x + threadIdx.x;
    if (i >= n4) return;
    float4 v = __ldg((const float4*)in + i);
    __half2 h0 = __floats2half2_rn(v.x, v.y);
    __half2 h1 = __floats2half2_rn(v.z, v.w);
    uint2 o;
    o.x = *(uint32_t*)&h0;
    o.y = *(uint32_t*)&h1;
    ((uint2*)out)[i] = o;
}

// transpose+convert layer-1 weights [k][n] fp32 -> [n][k] fp16
__global__ void wconv_kernel(const float* __restrict__ W1s, const float* __restrict__ W1n) {
    int t = blockIdx.x * blockDim.x + threadIdx.x;
    int m = t >> 14;
    int i = t & 16383;
    int n = i >> 7, k = i & 127;
    const float* W = (m == 0) ? W1s : W1n;
    g_w16[m][i] = __float2half_rn(__ldg(W + k * D + n));
}

// fused layer-2 weights: Wfs = W2s@Wc, Wfn = W2n@Wc, bf = b2@Wc + bc
__global__ void wfuse_kernel(const float* __restrict__ W2s, const float* __restrict__ W2n,
                             const float* __restrict__ Wc, const float* __restrict__ b2,
                             const float* __restrict__ bc) {
    int t = threadIdx.x;           // 512 threads, 1 block
    int which = t >> 8;
    int i = t & 255;
    int k = i >> 1, c = i & 1;
    const float* W = which ? W2n : W2s;
    float s = 0.f;
#pragma unroll 4
    for (int j = 0; j < D; j++) s += __ldg(W + k * D + j) * __ldg(Wc + j * 2 + c);
    if (which) g_wfn[i] = s; else g_wfs[i] = s;
    if (t < 2) {
        float sb = __ldg(bc + t);
        for (int j = 0; j < D; j++) sb += __ldg(b2 + j) * __ldg(Wc + j * 2 + t);
        g_bf[t] = sb;
    }
}

// ---------------------------------------------------------------- CSR build
__global__ void zero_cnt_kernel(int* __restrict__ cnt, int n) {
    int i = blockIdx.x * blockDim.x + threadIdx.x;
    if (i < n) cnt[i] = 0;
}

// histogram + per-edge local offset (kills the second atomic pass)
__global__ void hist_kernel(const int2* __restrict__ dst2, int* __restrict__ cnt,
                            int2* __restrict__ loc2, int E2) {
    int i = blockIdx.x * blockDim.x + threadIdx.x;
    if (i < E2) {
        int2 d = __ldg(dst2 + i);
        int p0 = atomicAdd(&cnt[d.x], 1);
        int p1 = atomicAdd(&cnt[d.y], 1);
        loc2[i] = make_int2(p0, p1);
    }
}

__global__ void scan_bsum_kernel(const int* __restrict__ cnt, int* __restrict__ bsum, int n) {
    __shared__ int sh[SCAN_B];
    int i = blockIdx.x * SCAN_B + threadIdx.x;
    sh[threadIdx.x] = (i < n) ? cnt[i] : 0;
    __syncthreads();
#pragma unroll
    for (int off = SCAN_B / 2; off; off >>= 1) {
        if (threadIdx.x < off) sh[threadIdx.x] += sh[threadIdx.x + off];
        __syncthreads();
    }
    if (threadIdx.x == 0) bsum[blockIdx.x] = sh[0];
}

__global__ void scan_top_kernel(int* __restrict__ bsum, int* __restrict__ rowstart,
                                int nb, int n) {
    __shared__ int sh[512];
    int t = threadIdx.x;
    int v = (t < nb) ? bsum[t] : 0;
    sh[t] = v;
    __syncthreads();
#pragma unroll
    for (int off = 1; off < 512; off <<= 1) {
        int u = (t >= off) ? sh[t - off] : 0;
        __syncthreads();
        sh[t] += u;
        __syncthreads();
    }
    if (t < nb) bsum[t] = sh[t] - v;
    if (t == 511) rowstart[n] = sh[511];
}

__global__ void scan_fin_kernel(const int* __restrict__ cnt, const int* __restrict__ bsum,
                                int* __restrict__ rowstart, int n) {
    __shared__ int sh[SCAN_B];
    int i = blockIdx.x * SCAN_B + threadIdx.x;
    int v = (i < n) ? cnt[i] : 0;
    sh[threadIdx.x] = v;
    __syncthreads();
#pragma unroll
    for (int off = 1; off < SCAN_B; off <<= 1) {
        int u = (threadIdx.x >= off) ? sh[threadIdx.x - off] : 0;
        __syncthreads();
        sh[threadIdx.x] += u;
        __syncthreads();
    }
    if (i < n) rowstart[i] = sh[threadIdx.x] - v + bsum[blockIdx.x];
}

// atomic-free scatter using precomputed local offsets
__global__ void fill2_kernel(const int2* __restrict__ src2, const int2* __restrict__ dst2,
                             const int2* __restrict__ loc2, const int* __restrict__ rowstart,
                             int* __restrict__ csrsrc, int E2) {
    int i = blockIdx.x * blockDim.x + threadIdx.x;
    if (i < E2) {
        int2 s = __ldg(src2 + i);
        int2 d = __ldg(dst2 + i);
        int2 l = __ldg(loc2 + i);
        csrsrc[__ldg(rowstart + d.x) + l.x] = s.x;
        csrsrc[__ldg(rowstart + d.y) + l.y] = s.y;
    }
}

// ---------------------------------------------------------------- layer-1 gather (chunked)
__global__ void gather16_kernel(const __half* __restrict__ H, const int* __restrict__ rowstart,
                                const int* __restrict__ csrsrc, __half* __restrict__ agg,
                                int base, int cnt) {
    int w = base + ((blockIdx.x * blockDim.x + threadIdx.x) >> 5);
    int lane = threadIdx.x & 31;
    if (w >= base + cnt) return;
    int beg = __ldg(rowstart + w);
    int end = __ldg(rowstart + w + 1);
    float2 a0 = make_float2(0.f, 0.f), a1 = make_float2(0.f, 0.f);
    float2 b0 = make_float2(0.f, 0.f), b1 = make_float2(0.f, 0.f);
    float2 c0 = make_float2(0.f, 0.f), c1 = make_float2(0.f, 0.f);
    float2 d0 = make_float2(0.f, 0.f), d1 = make_float2(0.f, 0.f);
    int i = beg;
    for (; i + 3 < end; i += 4) {
        int e0 = __ldg(csrsrc + i);
        int e1 = __ldg(csrsrc + i + 1);
        int e2 = __ldg(csrsrc + i + 2);
        int e3 = __ldg(csrsrc + i + 3);
        uint2 v0 = __ldg((const uint2*)(H + (size_t)e0 * D) + lane);
        uint2 v1 = __ldg((const uint2*)(H + (size_t)e1 * D) + lane);
        uint2 v2 = __ldg((const uint2*)(H + (size_t)e2 * D) + lane);
        uint2 v3 = __ldg((const uint2*)(H + (size_t)e3 * D) + lane);
        float2 p, q;
        p = __half22float2(*(__half2*)&v0.x); q = __half22float2(*(__half2*)&v0.y);
        a0.x += p.x; a0.y += p.y; a1.x += q.x; a1.y += q.y;
        p = __half22float2(*(__half2*)&v1.x); q = __half22float2(*(__half2*)&v1.y);
        b0.x += p.x; b0.y += p.y; b1.x += q.x; b1.y += q.y;
        p = __half22float2(*(__half2*)&v2.x); q = __half22float2(*(__half2*)&v2.y);
        c0.x += p.x; c0.y += p.y; c1.x += q.x; c1.y += q.y;
        p = __half22float2(*(__half2*)&v3.x); q = __half22float2(*(__half2*)&v3.y);
        d0.x += p.x; d0.y += p.y; d1.x += q.x; d1.y += q.y;
    }
    for (; i < end; i++) {
        int e0 = __ldg(csrsrc + i);
        uint2 v0 = __ldg((const uint2*)(H + (size_t)e0 * D) + lane);
        float2 p = __half22float2(*(__half2*)&v0.x);
        float2 q = __half22float2(*(__half2*)&v0.y);
        a0.x += p.x; a0.y += p.y; a1.x += q.x; a1.y += q.y;
    }
    float inv = 1.0f / (float)max(end - beg, 1);
    __half2 o0 = __floats2half2_rn((a0.x + b0.x + c0.x + d0.x) * inv,
                                   (a0.y + b0.y + c0.y + d0.y) * inv);
    __half2 o1 = __floats2half2_rn((a1.x + b1.x + c1.x + d1.x) * inv,
                                   (a1.y + b1.y + c1.y + d1.y) * inv);
    uint2 o;
    o.x = *(uint32_t*)&o0;
    o.y = *(uint32_t*)&o1;
    *((uint2*)(agg + (size_t)w * D) + lane) = o;
}

// ---------------------------------------------------------------- layer-1 GEMM + z epilogue
// h = relu( feat @ W1s + agg @ W1n + b1 )  [fp32, registers only]
// z[r] = ( h@Wfs , h@Wfn ). h is never materialized.
#define CHUNK_WORDS (128 * 32)
__global__ void __launch_bounds__(256, 2)
gemm_sage_f16(const __half* __restrict__ Aself, const __half* __restrict__ Aagg,
              const __half* __restrict__ Wself, const __half* __restrict__ Wneigh,
              const float* __restrict__ bias, int M,
              const float* __restrict__ Wfs, const float* __restrict__ Wfn,
              float* __restrict__ z) {
    extern __shared__ __align__(16) uint32_t dyn[];
    uint32_t* Abuf[2] = {dyn, dyn + CHUNK_WORDS};
    uint32_t* Bbuf[2] = {dyn + 2 * CHUNK_WORDS, dyn + 3 * CHUNK_WORDS};
    __shared__ float s_z[2][128][4];

    int tid = threadIdx.x;
    int wid = tid >> 5;
    int lane = tid & 31;
    int wm = wid >> 1;
    int wn = wid & 1;
    int row0 = blockIdx.x * 128;

    const __half* Aarr[2] = {Aself, Aagg};
    const __half* Warr[2] = {Wself, Wneigh};

    float acc[2][8][4];
#pragma unroll
    for (int mt = 0; mt < 2; mt++)
#pragma unroll
        for (int nt = 0; nt < 8; nt++)
#pragma unroll
            for (int e = 0; e < 4; e++) acc[mt][nt][e] = 0.f;

    int s_r = tid >> 3;
    int s_v = tid & 7;
    uint32_t a_sm[2], b_sm[2];
#pragma unroll
    for (int b = 0; b < 2; b++) {
        a_sm[b] = (uint32_t)__cvta_generic_to_shared(Abuf[b]);
        b_sm[b] = (uint32_t)__cvta_generic_to_shared(Bbuf[b]);
    }

    int r0l = wm * 32 + (lane >> 2);
    int wlo = lane & 3;
    int n_row = wn * 64 + (lane >> 2);

    {
#pragma unroll
        for (int it = 0; it < 4; it++) {
            int r = s_r + it * 32;
            int gr = min(row0 + r, M - 1);
            uint32_t off = (uint32_t)((r * 8 + (s_v ^ (r & 7))) * 16);
            cp16(a_sm[0] + off, Aarr[0] + (size_t)gr * D + s_v * 8);
            cp16(b_sm[0] + off, Warr[0] + (size_t)r * D + s_v * 8);
        }
        CP_COMMIT();
    }

#pragma unroll 1
    for (int step = 0; step < 4; ++step) {
        if (step < 3) {
            int ns = step + 1;
            const __half* A = Aarr[ns >> 1];
            const __half* W = Warr[ns >> 1];
            int k0 = (ns & 1) * 64;
            int nb = ns & 1;
#pragma unroll
            for (int it = 0; it < 4; it++) {
                int r = s_r + it * 32;
                int gr = min(row0 + r, M - 1);
                uint32_t off = (uint32_t)((r * 8 + (s_v ^ (r & 7))) * 16);
                cp16(a_sm[nb] + off, A + (size_t)gr * D + k0 + s_v * 8);
                cp16(b_sm[nb] + off, W + (size_t)r * D + k0 + s_v * 8);
            }
            CP_COMMIT();
            CP_WAIT(1);
        } else {
            CP_WAIT(0);
        }
        __syncthreads();

        const uint32_t* As = Abuf[step & 1];
        const uint32_t* Bs = Bbuf[step & 1];
#pragma unroll
        for (int ks = 0; ks < 4; ks++) {
            uint32_t af[2][4];
#pragma unroll
            for (int mt = 0; mt < 2; mt++) {
                int r = r0l + mt * 16;
                int sw = r & 7;
                int v0 = (2 * ks) ^ sw, v1 = (2 * ks + 1) ^ sw;
                af[mt][0] = As[r * 32 + v0 * 4 + wlo];
                af[mt][1] = As[(r + 8) * 32 + v0 * 4 + wlo];
                af[mt][2] = As[r * 32 + v1 * 4 + wlo];
                af[mt][3] = As[(r + 8) * 32 + v1 * 4 + wlo];
            }
#pragma unroll
            for (int nt = 0; nt < 8; nt++) {
                int n = n_row + nt * 8;
                int swn = n & 7;
                uint32_t b2[2];
                b2[0] = Bs[n * 32 + ((2 * ks) ^ swn) * 4 + wlo];
                b2[1] = Bs[n * 32 + ((2 * ks + 1) ^ swn) * 4 + wlo];
#pragma unroll
                for (int mt = 0; mt < 2; mt++)
                    mma_f16(acc[mt][nt], af[mt], b2);
            }
        }
        __syncthreads();
    }

    // ---- z epilogue ----
#pragma unroll
    for (int mt = 0; mt < 2; mt++) {
        float zsl0 = 0.f, zsl1 = 0.f, znl0 = 0.f, znl1 = 0.f;
        float zsh0 = 0.f, zsh1 = 0.f, znh0 = 0.f, znh1 = 0.f;
#pragma unroll
        for (int nt = 0; nt < 8; nt++) {
            int c = wn * 64 + nt * 8 + (lane & 3) * 2;
            float b0 = __ldg(bias + c), b1 = __ldg(bias + c + 1);
            float2 ws0 = __ldg((const float2*)(Wfs + (size_t)c * 2));
            float2 ws1 = __ldg((const float2*)(Wfs + (size_t)(c + 1) * 2));
            float2 wn0 = __ldg((const float2*)(Wfn + (size_t)c * 2));
            float2 wn1 = __ldg((const float2*)(Wfn + (size_t)(c + 1) * 2));
            float h0 = fmaxf(acc[mt][nt][0] + b0, 0.f);
            float h1 = fmaxf(acc[mt][nt][1] + b1, 0.f);
            float h2 = fmaxf(acc[mt][nt][2] + b0, 0.f);
            float h3 = fmaxf(acc[mt][nt][3] + b1, 0.f);
            zsl0 += h0 * ws0.x + h1 * ws1.x;  zsl1 += h0 * ws0.y + h1 * ws1.y;
            znl0 += h0 * wn0.x + h1 * wn1.x;  znl1 += h0 * wn0.y + h1 * wn1.y;
            zsh0 += h2 * ws0.x + h3 * ws1.x;  zsh1 += h2 * ws0.y + h3 * ws1.y;
            znh0 += h2 * wn0.x + h3 * wn1.x;  znh1 += h2 * wn0.y + h3 * wn1.y;
        }
#pragma unroll
        for (int off = 1; off <= 2; off <<= 1) {
            zsl0 += __shfl_xor_sync(0xFFFFFFFFu, zsl0, off);
            zsl1 += __shfl_xor_sync(0xFFFFFFFFu, zsl1, off);
            znl0 += __shfl_xor_sync(0xFFFFFFFFu, znl0, off);
            znl1 += __shfl_xor_sync(0xFFFFFFFFu, znl1, off);
            zsh0 += __shfl_xor_sync(0xFFFFFFFFu, zsh0, off);
            zsh1 += __shfl_xor_sync(0xFFFFFFFFu, zsh1, off);
            znh0 += __shfl_xor_sync(0xFFFFFFFFu, znh0, off);
            znh1 += __shfl_xor_sync(0xFFFFFFFFu, znh1, off);
        }
        if ((lane & 3) == 0) {
            int lr = wm * 32 + mt * 16 + (lane >> 2);
            s_z[wn][lr][0] = zsl0; s_z[wn][lr][1] = zsl1;
            s_z[wn][lr][2] = znl0; s_z[wn][lr][3] = znl1;
            s_z[wn][lr + 8][0] = zsh0; s_z[wn][lr + 8][1] = zsh1;
            s_z[wn][lr + 8][2] = znh0; s_z[wn][lr + 8][3] = znh1;
        }
    }
    __syncthreads();
    {
        int row = tid >> 1;
        int j = tid & 1;
        if (row0 + row < M) {
            float2 v;
            v.x = s_z[0][row][j * 2 + 0] + s_z[1][row][j * 2 + 0];
            v.y = s_z[0][row][j * 2 + 1] + s_z[1][row][j * 2 + 1];
            *(float2*)(z + (size_t)(row0 + row) * 4 + j * 2) = v;
        }
    }
}

// ---------------------------------------------------------------- final: 8-byte edge gather
__global__ void final_kernel(const float* __restrict__ z, const int* __restrict__ rowstart,
                             const int* __restrict__ csrsrc, const float* __restrict__ bf,
                             float* __restrict__ out, int N) {
    int m = blockIdx.x * blockDim.x + threadIdx.x;
    if (m >= N) return;
    int beg = __ldg(rowstart + m);
    int end = __ldg(rowstart + m + 1);
    float s0 = 0.f, s1 = 0.f, t0 = 0.f, t1 = 0.f;
    int i = beg;
    for (; i + 1 < end; i += 2) {
        int e0 = __ldg(csrsrc + i);
        int e1 = __ldg(csrsrc + i + 1);
        float2 z0 = __ldg((const float2*)(z + (size_t)e0 * 4) + 1);
        float2 z1 = __ldg((const float2*)(z + (size_t)e1 * 4) + 1);
        s0 += z0.x; s1 += z0.y;
        t0 += z1.x; t1 += z1.y;
    }
    if (i < end) {
        int e0 = __ldg(csrsrc + i);
        float2 z0 = __ldg((const float2*)(z + (size_t)e0 * 4) + 1);
        s0 += z0.x; s1 += z0.y;
    }
    float inv = 1.0f / (float)max(end - beg, 1);
    float2 zs = __ldg((const float2*)(z + (size_t)m * 4));
    out[(size_t)m * 2 + 0] = zs.x + (s0 + t0) * inv + __ldg(bf);
    out[(size_t)m * 2 + 1] = zs.y + (s1 + t1) * inv + __ldg(bf + 1);
}

// ---------------------------------------------------------------- launch
extern "C" void kernel_launch(void* const* d_in, const int* in_sizes, int n_in,
                              void* d_out, int out_size) {
    const float* features = (const float*)d_in[0];
    const int*   src      = (const int*)d_in[1];
    const int*   dst      = (const int*)d_in[2];
    const float* W1s      = (const float*)d_in[3];
    const float* W1n      = (const float*)d_in[4];
    const float* b1       = (const float*)d_in[5];
    const float* W2s      = (const float*)d_in[6];
    const float* W2n      = (const float*)d_in[7];
    const float* b2       = (const float*)d_in[8];
    const float* Wc       = (const float*)d_in[9];
    const float* bc       = (const float*)d_in[10];

    int N = in_sizes[0] / D;
    int E = in_sizes[1];

    int *cnt, *rowstart, *csrsrc, *bsum, *locoff;
    float *wfs, *wfn, *bf, *zbuf;
    __half *feat16, *agg16, *w16;
    cudaGetSymbolAddress((void**)&cnt, g_cnt);
    cudaGetSymbolAddress((void**)&rowstart, g_rowstart);
    cudaGetSymbolAddress((void**)&csrsrc, g_csrsrc);
    cudaGetSymbolAddress((void**)&bsum, g_bsum);
    cudaGetSymbolAddress((void**)&locoff, g_locoff);
    cudaGetSymbolAddress((void**)&wfs, g_wfs);
    cudaGetSymbolAddress((void**)&wfn, g_wfn);
    cudaGetSymbolAddress((void**)&bf, g_bf);
    cudaGetSymbolAddress((void**)&zbuf, g_z);
    cudaGetSymbolAddress((void**)&feat16, g_feat16);
    cudaGetSymbolAddress((void**)&agg16, g_agg16);
    cudaGetSymbolAddress((void**)&w16, g_w16);

    static cudaStream_t s1 = nullptr;
    static cudaEvent_t evFill = nullptr, evG0 = nullptr, evG1 = nullptr, ev0 = nullptr;
    static int init_done = 0;
    if (!init_done) {
        cudaFuncSetAttribute(gemm_sage_f16,
                             cudaFuncAttributeMaxDynamicSharedMemorySize, 65536);
        if (cudaStreamCreateWithFlags(&s1, cudaStreamNonBlocking) != cudaSuccess) s1 = nullptr;
        if (s1) {
            cudaEventCreateWithFlags(&ev0, cudaEventDisableTiming);
            cudaEventCreateWithFlags(&evFill, cudaEventDisableTiming);
            cudaEventCreateWithFlags(&evG0, cudaEventDisableTiming);
            cudaEventCreateWithFlags(&evG1, cudaEventDisableTiming);
        }
        init_done = 1;
    }

    int mblocks = (N + 127) / 128;       // 782
    int n4 = N * (D / 4);
    int nb = (N + SCAN_B - 1) / SCAN_B;
    const int SMEM = 65536;

    // chunk split (multiples of 128)
    int blk0 = mblocks / 2;              // 391
    int base0 = 0, cnt0 = blk0 * 128;    // 50048
    int base1 = cnt0, cnt1 = N - cnt0;   // 49952
    int blk1 = mblocks - blk0;
    int gblk0 = (cnt0 + 7) / 8, gblk1 = (cnt1 + 7) / 8;

    cudaStream_t cs = s1 ? s1 : (cudaStream_t)0;
    if (s1) {
        cudaEventRecord(ev0, 0);
        cudaStreamWaitEvent(s1, ev0, 0);
    }
    // side stream: conversions + fused layer-2 weights (no CSR deps)
    conv16_kernel<<<(n4 + 255) / 256, 256, 0, cs>>>(features, feat16, n4);
    wconv_kernel<<<(2 * D * D + 255) / 256, 256, 0, cs>>>(W1s, W1n);
    wfuse_kernel<<<1, 512, 0, cs>>>(W2s, W2n, Wc, b2, bc);

    // main stream: CSR build
    zero_cnt_kernel<<<(N + 255) / 256, 256>>>(cnt, N);
    hist_kernel<<<(E / 2 + 255) / 256, 256>>>((const int2*)dst, cnt, (int2*)locoff, E / 2);
    scan_bsum_kernel<<<nb, SCAN_B>>>(cnt, bsum, N);
    scan_top_kernel<<<1, 512>>>(bsum, rowstart, nb, N);
    scan_fin_kernel<<<nb, SCAN_B>>>(cnt, bsum, rowstart, N);
    fill2_kernel<<<(E / 2 + 255) / 256, 256>>>((const int2*)src, (const int2*)dst,
                                               (const int2*)locoff, rowstart, csrsrc, E / 2);

    if (s1) {
        cudaEventRecord(evFill, 0);
        cudaStreamWaitEvent(s1, evFill, 0);
        // gathers on side stream (after conv16, serial on s1)
        gather16_kernel<<<gblk0, 256, 0, s1>>>(feat16, rowstart, csrsrc, agg16, base0, cnt0);
        cudaEventRecord(evG0, s1);
        gather16_kernel<<<gblk1, 256, 0, s1>>>(feat16, rowstart, csrsrc, agg16, base1, cnt1);
        cudaEventRecord(evG1, s1);
        // gemms on main, overlapping gather of the other chunk
        cudaStreamWaitEvent((cudaStream_t)0, evG0, 0);
        gemm_sage_f16<<<blk0, 256, SMEM>>>(feat16 + (size_t)base0 * D, agg16 + (size_t)base0 * D,
                                           w16, w16 + D * D, b1, cnt0, wfs, wfn,
                                           zbuf + (size_t)base0 * 4);
        cudaStreamWaitEvent((cudaStream_t)0, evG1, 0);
        gemm_sage_f16<<<blk1, 256, SMEM>>>(feat16 + (size_t)base1 * D, agg16 + (size_t)base1 * D,
                                           w16, w16 + D * D, b1, cnt1, wfs, wfn,
                                           zbuf + (size_t)base1 * 4);
    } else {
        gather16_kernel<<<gblk0 + gblk1, 256>>>(feat16, rowstart, csrsrc, agg16, 0, N);
        gemm_sage_f16<<<mblocks, 256, SMEM>>>(feat16, agg16, w16, w16 + D * D,
                                              b1, N, wfs, wfn, zbuf);
    }
    final_kernel<<<(N + 255) / 256, 256>>>(zbuf, rowstart, csrsrc, bf,
                                           (float*)d_out, N);
}

// round 15
// speedup vs baseline: 1.0051x; 1.0051x over previous
#include <cuda_runtime.h>
#include <cuda_fp16.h>
#include <cstdint>

#define N_NODES 100000
#define N_EDGES 1600000
#define D 128
#define SCAN_B 256

// Scratch (allocation-free: __device__ globals)
__device__ int    g_cnt[N_NODES];
__device__ int    g_rowstart[N_NODES + 1];
__device__ int    g_bsum[1024];
__device__ int    g_locoff[N_EDGES];
__device__ int    g_csrsrc[N_EDGES];
__device__ float  g_wfs[D * 2];
__device__ float  g_wfn[D * 2];
__device__ float  g_bf[2];
__device__ __align__(16) float g_z[(size_t)N_NODES * 4];  // [self0,self1,neigh0,neigh1]
__device__ __align__(128) __half g_feat16[(size_t)N_NODES * D];
__device__ __align__(128) __half g_agg16[(size_t)N_NODES * D];
__device__ __align__(128) __half g_w16[2][D * D];  // W1s^T, W1n^T (n-major)

// ---------------------------------------------------------------- helpers
__device__ __forceinline__ void mma_f16(float* d, const uint32_t* a, const uint32_t* b) {
    asm volatile(
        "mma.sync.aligned.m16n8k16.row.col.f32.f16.f16.f32 "
        "{%0,%1,%2,%3}, {%4,%5,%6,%7}, {%8,%9}, {%0,%1,%2,%3};"
        : "+f"(d[0]), "+f"(d[1]), "+f"(d[2]), "+f"(d[3])
        : "r"(a[0]), "r"(a[1]), "r"(a[2]), "r"(a[3]), "r"(b[0]), "r"(b[1]));
}
__device__ __forceinline__ void cp16(uint32_t dst, const void* src) {
    asm volatile("cp.async.cg.shared.global [%0], [%1], 16;" :: "r"(dst), "l"(src));
}
#define CP_COMMIT() asm volatile("cp.async.commit_group;" ::: "memory")
#define CP_WAIT(n)  asm volatile("cp.async.wait_group %0;" :: "n"(n) : "memory")

// ---------------------------------------------------------------- conversions
__global__ void conv16_kernel(const float* __restrict__ in, __half* __restrict__ out, int n4) {
    int i = blockIdx.x * blockDim.x + threadIdx.x;
    if (i >= n4) return;
    float4 v = __ldg((const float4*)in + i);
    __half2 h0 = __floats2half2_rn(v.x, v.y);
    __half2 h1 = __floats2half2_rn(v.z, v.w);
    uint2 o;
    o.x = *(uint32_t*)&h0;
    o.y = *(uint32_t*)&h1;
    ((uint2*)out)[i] = o;
}

// transpose+convert layer-1 weights [k][n] fp32 -> [n][k] fp16
__global__ void wconv_kernel(const float* __restrict__ W1s, const float* __restrict__ W1n) {
    int t = blockIdx.x * blockDim.x + threadIdx.x;
    int m = t >> 14;
    int i = t & 16383;
    int n = i >> 7, k = i & 127;
    const float* W = (m == 0) ? W1s : W1n;
    g_w16[m][i] = __float2half_rn(__ldg(W + k * D + n));
}

// fused layer-2 weights: Wfs = W2s@Wc, Wfn = W2n@Wc, bf = b2@Wc + bc
__global__ void wfuse_kernel(const float* __restrict__ W2s, const float* __restrict__ W2n,
                             const float* __restrict__ Wc, const float* __restrict__ b2,
                             const float* __restrict__ bc) {
    int t = threadIdx.x;           // 512 threads, 1 block
    int which = t >> 8;
    int i = t & 255;
    int k = i >> 1, c = i & 1;
    const float* W = which ? W2n : W2s;
    float s = 0.f;
#pragma unroll 4
    for (int j = 0; j < D; j++) s += __ldg(W + k * D + j) * __ldg(Wc + j * 2 + c);
    if (which) g_wfn[i] = s; else g_wfs[i] = s;
    if (t < 2) {
        float sb = __ldg(bc + t);
        for (int j = 0; j < D; j++) sb += __ldg(b2 + j) * __ldg(Wc + j * 2 + t);
        g_bf[t] = sb;
    }
}

// ---------------------------------------------------------------- CSR build
// histogram + per-edge local offset (no second atomic pass needed)
__global__ void hist_kernel(const int2* __restrict__ dst2, int* __restrict__ cnt,
                            int2* __restrict__ loc2, int E2) {
    int i = blockIdx.x * blockDim.x + threadIdx.x;
    if (i < E2) {
        int2 d = __ldg(dst2 + i);
        int p0 = atomicAdd(&cnt[d.x], 1);
        int p1 = atomicAdd(&cnt[d.y], 1);
        loc2[i] = make_int2(p0, p1);
    }
}

__global__ void scan_bsum_kernel(const int* __restrict__ cnt, int* __restrict__ bsum, int n) {
    __shared__ int sh[SCAN_B];
    int i = blockIdx.x * SCAN_B + threadIdx.x;
    sh[threadIdx.x] = (i < n) ? cnt[i] : 0;
    __syncthreads();
#pragma unroll
    for (int off = SCAN_B / 2; off; off >>= 1) {
        if (threadIdx.x < off) sh[threadIdx.x] += sh[threadIdx.x + off];
        __syncthreads();
    }
    if (threadIdx.x == 0) bsum[blockIdx.x] = sh[0];
}

__global__ void scan_top_kernel(int* __restrict__ bsum, int* __restrict__ rowstart,
                                int nb, int n) {
    __shared__ int sh[512];
    int t = threadIdx.x;
    int v = (t < nb) ? bsum[t] : 0;
    sh[t] = v;
    __syncthreads();
#pragma unroll
    for (int off = 1; off < 512; off <<= 1) {
        int u = (t >= off) ? sh[t - off] : 0;
        __syncthreads();
        sh[t] += u;
        __syncthreads();
    }
    if (t < nb) bsum[t] = sh[t] - v;
    if (t == 511) rowstart[n] = sh[511];
}

__global__ void scan_fin_kernel(const int* __restrict__ cnt, const int* __restrict__ bsum,
                                int* __restrict__ rowstart, int n) {
    __shared__ int sh[SCAN_B];
    int i = blockIdx.x * SCAN_B + threadIdx.x;
    int v = (i < n) ? cnt[i] : 0;
    sh[threadIdx.x] = v;
    __syncthreads();
#pragma unroll
    for (int off = 1; off < SCAN_B; off <<= 1) {
        int u = (threadIdx.x >= off) ? sh[threadIdx.x - off] : 0;
        __syncthreads();
        sh[threadIdx.x] += u;
        __syncthreads();
    }
    if (i < n) rowstart[i] = sh[threadIdx.x] - v + bsum[blockIdx.x];
}

// atomic-free scatter using precomputed local offsets
__global__ void fill2_kernel(const int2* __restrict__ src2, const int2* __restrict__ dst2,
                             const int2* __restrict__ loc2, const int* __restrict__ rowstart,
                             int* __restrict__ csrsrc, int E2) {
    int i = blockIdx.x * blockDim.x + threadIdx.x;
    if (i < E2) {
        int2 s = __ldg(src2 + i);
        int2 d = __ldg(dst2 + i);
        int2 l = __ldg(loc2 + i);
        csrsrc[__ldg(rowstart + d.x) + l.x] = s.x;
        csrsrc[__ldg(rowstart + d.y) + l.y] = s.y;
    }
}

// ---------------------------------------------------------------- layer-1 gather
__global__ void gather16_kernel(const __half* __restrict__ H, const int* __restrict__ rowstart,
                                const int* __restrict__ csrsrc, __half* __restrict__ agg, int N) {
    int w = (blockIdx.x * blockDim.x + threadIdx.x) >> 5;
    int lane = threadIdx.x & 31;
    if (w >= N) return;
    int beg = __ldg(rowstart + w);
    int end = __ldg(rowstart + w + 1);
    float2 a0 = make_float2(0.f, 0.f), a1 = make_float2(0.f, 0.f);
    float2 b0 = make_float2(0.f, 0.f), b1 = make_float2(0.f, 0.f);
    float2 c0 = make_float2(0.f, 0.f), c1 = make_float2(0.f, 0.f);
    float2 d0 = make_float2(0.f, 0.f), d1 = make_float2(0.f, 0.f);
    int i = beg;
    for (; i + 3 < end; i += 4) {
        int e0 = __ldg(csrsrc + i);
        int e1 = __ldg(csrsrc + i + 1);
        int e2 = __ldg(csrsrc + i + 2);
        int e3 = __ldg(csrsrc + i + 3);
        uint2 v0 = __ldg((const uint2*)(H + (size_t)e0 * D) + lane);
        uint2 v1 = __ldg((const uint2*)(H + (size_t)e1 * D) + lane);
        uint2 v2 = __ldg((const uint2*)(H + (size_t)e2 * D) + lane);
        uint2 v3 = __ldg((const uint2*)(H + (size_t)e3 * D) + lane);
        float2 p, q;
        p = __half22float2(*(__half2*)&v0.x); q = __half22float2(*(__half2*)&v0.y);
        a0.x += p.x; a0.y += p.y; a1.x += q.x; a1.y += q.y;
        p = __half22float2(*(__half2*)&v1.x); q = __half22float2(*(__half2*)&v1.y);
        b0.x += p.x; b0.y += p.y; b1.x += q.x; b1.y += q.y;
        p = __half22float2(*(__half2*)&v2.x); q = __half22float2(*(__half2*)&v2.y);
        c0.x += p.x; c0.y += p.y; c1.x += q.x; c1.y += q.y;
        p = __half22float2(*(__half2*)&v3.x); q = __half22float2(*(__half2*)&v3.y);
        d0.x += p.x; d0.y += p.y; d1.x += q.x; d1.y += q.y;
    }
    for (; i < end; i++) {
        int e0 = __ldg(csrsrc + i);
        uint2 v0 = __ldg((const uint2*)(H + (size_t)e0 * D) + lane);
        float2 p = __half22float2(*(__half2*)&v0.x);
        float2 q = __half22float2(*(__half2*)&v0.y);
        a0.x += p.x; a0.y += p.y; a1.x += q.x; a1.y += q.y;
    }
    float inv = 1.0f / (float)max(end - beg, 1);
    __half2 o0 = __floats2half2_rn((a0.x + b0.x + c0.x + d0.x) * inv,
                                   (a0.y + b0.y + c0.y + d0.y) * inv);
    __half2 o1 = __floats2half2_rn((a1.x + b1.x + c1.x + d1.x) * inv,
                                   (a1.y + b1.y + c1.y + d1.y) * inv);
    uint2 o;
    o.x = *(uint32_t*)&o0;
    o.y = *(uint32_t*)&o1;
    *((uint2*)(agg + (size_t)w * D) + lane) = o;
}

// ---------------------------------------------------------------- layer-1 GEMM + z epilogue
// h = relu( feat @ W1s + agg @ W1n + b1 )  [fp32, registers only]
// z[r] = ( h@Wfs , h@Wfn ). h is never materialized.
#define CHUNK_WORDS (128 * 32)
__global__ void __launch_bounds__(256, 2)
gemm_sage_f16(const __half* __restrict__ Aself, const __half* __restrict__ Aagg,
              const __half* __restrict__ Wself, const __half* __restrict__ Wneigh,
              const float* __restrict__ bias, int M,
              const float* __restrict__ Wfs, const float* __restrict__ Wfn,
              float* __restrict__ z) {
    extern __shared__ __align__(16) uint32_t dyn[];
    uint32_t* Abuf[2] = {dyn, dyn + CHUNK_WORDS};
    uint32_t* Bbuf[2] = {dyn + 2 * CHUNK_WORDS, dyn + 3 * CHUNK_WORDS};
    __shared__ float s_z[2][128][4];

    int tid = threadIdx.x;
    int wid = tid >> 5;
    int lane = tid & 31;
    int wm = wid >> 1;
    int wn = wid & 1;
    int row0 = blockIdx.x * 128;

    const __half* Aarr[2] = {Aself, Aagg};
    const __half* Warr[2] = {Wself, Wneigh};

    float acc[2][8][4];
#pragma unroll
    for (int mt = 0; mt < 2; mt++)
#pragma unroll
        for (int nt = 0; nt < 8; nt++)
#pragma unroll
            for (int e = 0; e < 4; e++) acc[mt][nt][e] = 0.f;

    int s_r = tid >> 3;
    int s_v = tid & 7;
    uint32_t a_sm[2], b_sm[2];
#pragma unroll
    for (int b = 0; b < 2; b++) {
        a_sm[b] = (uint32_t)__cvta_generic_to_shared(Abuf[b]);
        b_sm[b] = (uint32_t)__cvta_generic_to_shared(Bbuf[b]);
    }

    int r0l = wm * 32 + (lane >> 2);
    int wlo = lane & 3;
    int n_row = wn * 64 + (lane >> 2);

    {
#pragma unroll
        for (int it = 0; it < 4; it++) {
            int r = s_r + it * 32;
            int gr = min(row0 + r, M - 1);
            uint32_t off = (uint32_t)((r * 8 + (s_v ^ (r & 7))) * 16);
            cp16(a_sm[0] + off, Aarr[0] + (size_t)gr * D + s_v * 8);
            cp16(b_sm[0] + off, Warr[0] + (size_t)r * D + s_v * 8);
        }
        CP_COMMIT();
    }

#pragma unroll 1
    for (int step = 0; step < 4; ++step) {
        if (step < 3) {
            int ns = step + 1;
            const __half* A = Aarr[ns >> 1];
            const __half* W = Warr[ns >> 1];
            int k0 = (ns & 1) * 64;
            int nb = ns & 1;
#pragma unroll
            for (int it = 0; it < 4; it++) {
                int r = s_r + it * 32;
                int gr = min(row0 + r, M - 1);
                uint32_t off = (uint32_t)((r * 8 + (s_v ^ (r & 7))) * 16);
                cp16(a_sm[nb] + off, A + (size_t)gr * D + k0 + s_v * 8);
                cp16(b_sm[nb] + off, W + (size_t)r * D + k0 + s_v * 8);
            }
            CP_COMMIT();
            CP_WAIT(1);
        } else {
            CP_WAIT(0);
        }
        __syncthreads();

        const uint32_t* As = Abuf[step & 1];
        const uint32_t* Bs = Bbuf[step & 1];
#pragma unroll
        for (int ks = 0; ks < 4; ks++) {
            uint32_t af[2][4];
#pragma unroll
            for (int mt = 0; mt < 2; mt++) {
                int r = r0l + mt * 16;
                int sw = r & 7;
                int v0 = (2 * ks) ^ sw, v1 = (2 * ks + 1) ^ sw;
                af[mt][0] = As[r * 32 + v0 * 4 + wlo];
                af[mt][1] = As[(r + 8) * 32 + v0 * 4 + wlo];
                af[mt][2] = As[r * 32 + v1 * 4 + wlo];
                af[mt][3] = As[(r + 8) * 32 + v1 * 4 + wlo];
            }
#pragma unroll
            for (int nt = 0; nt < 8; nt++) {
                int n = n_row + nt * 8;
                int swn = n & 7;
                uint32_t b2[2];
                b2[0] = Bs[n * 32 + ((2 * ks) ^ swn) * 4 + wlo];
                b2[1] = Bs[n * 32 + ((2 * ks + 1) ^ swn) * 4 + wlo];
#pragma unroll
                for (int mt = 0; mt < 2; mt++)
                    mma_f16(acc[mt][nt], af[mt], b2);
            }
        }
        __syncthreads();
    }

    // ---- z epilogue ----
#pragma unroll
    for (int mt = 0; mt < 2; mt++) {
        float zsl0 = 0.f, zsl1 = 0.f, znl0 = 0.f, znl1 = 0.f;
        float zsh0 = 0.f, zsh1 = 0.f, znh0 = 0.f, znh1 = 0.f;
#pragma unroll
        for (int nt = 0; nt < 8; nt++) {
            int c = wn * 64 + nt * 8 + (lane & 3) * 2;
            float b0 = __ldg(bias + c), b1 = __ldg(bias + c + 1);
            float2 ws0 = __ldg((const float2*)(Wfs + (size_t)c * 2));
            float2 ws1 = __ldg((const float2*)(Wfs + (size_t)(c + 1) * 2));
            float2 wn0 = __ldg((const float2*)(Wfn + (size_t)c * 2));
            float2 wn1 = __ldg((const float2*)(Wfn + (size_t)(c + 1) * 2));
            float h0 = fmaxf(acc[mt][nt][0] + b0, 0.f);
            float h1 = fmaxf(acc[mt][nt][1] + b1, 0.f);
            float h2 = fmaxf(acc[mt][nt][2] + b0, 0.f);
            float h3 = fmaxf(acc[mt][nt][3] + b1, 0.f);
            zsl0 += h0 * ws0.x + h1 * ws1.x;  zsl1 += h0 * ws0.y + h1 * ws1.y;
            znl0 += h0 * wn0.x + h1 * wn1.x;  znl1 += h0 * wn0.y + h1 * wn1.y;
            zsh0 += h2 * ws0.x + h3 * ws1.x;  zsh1 += h2 * ws0.y + h3 * ws1.y;
            znh0 += h2 * wn0.x + h3 * wn1.x;  znh1 += h2 * wn0.y + h3 * wn1.y;
        }
#pragma unroll
        for (int off = 1; off <= 2; off <<= 1) {
            zsl0 += __shfl_xor_sync(0xFFFFFFFFu, zsl0, off);
            zsl1 += __shfl_xor_sync(0xFFFFFFFFu, zsl1, off);
            znl0 += __shfl_xor_sync(0xFFFFFFFFu, znl0, off);
            znl1 += __shfl_xor_sync(0xFFFFFFFFu, znl1, off);
            zsh0 += __shfl_xor_sync(0xFFFFFFFFu, zsh0, off);
            zsh1 += __shfl_xor_sync(0xFFFFFFFFu, zsh1, off);
            znh0 += __shfl_xor_sync(0xFFFFFFFFu, znh0, off);
            znh1 += __shfl_xor_sync(0xFFFFFFFFu, znh1, off);
        }
        if ((lane & 3) == 0) {
            int lr = wm * 32 + mt * 16 + (lane >> 2);
            s_z[wn][lr][0] = zsl0; s_z[wn][lr][1] = zsl1;
            s_z[wn][lr][2] = znl0; s_z[wn][lr][3] = znl1;
            s_z[wn][lr + 8][0] = zsh0; s_z[wn][lr + 8][1] = zsh1;
            s_z[wn][lr + 8][2] = znh0; s_z[wn][lr + 8][3] = znh1;
        }
    }
    __syncthreads();
    {
        int row = tid >> 1;
        int j = tid & 1;
        if (row0 + row < M) {
            float2 v;
            v.x = s_z[0][row][j * 2 + 0] + s_z[1][row][j * 2 + 0];
            v.y = s_z[0][row][j * 2 + 1] + s_z[1][row][j * 2 + 1];
            *(float2*)(z + (size_t)(row0 + row) * 4 + j * 2) = v;
        }
    }
}

// ---------------------------------------------------------------- final: 8-byte edge gather
__global__ void final_kernel(const float* __restrict__ z, const int* __restrict__ rowstart,
                             const int* __restrict__ csrsrc, const float* __restrict__ bf,
                             float* __restrict__ out, int N) {
    int m = blockIdx.x * blockDim.x + threadIdx.x;
    if (m >= N) return;
    int beg = __ldg(rowstart + m);
    int end = __ldg(rowstart + m + 1);
    float s0 = 0.f, s1 = 0.f, t0 = 0.f, t1 = 0.f;
    int i = beg;
    for (; i + 1 < end; i += 2) {
        int e0 = __ldg(csrsrc + i);
        int e1 = __ldg(csrsrc + i + 1);
        float2 z0 = __ldg((const float2*)(z + (size_t)e0 * 4) + 1);
        float2 z1 = __ldg((const float2*)(z + (size_t)e1 * 4) + 1);
        s0 += z0.x; s1 += z0.y;
        t0 += z1.x; t1 += z1.y;
    }
    if (i < end) {
        int e0 = __ldg(csrsrc + i);
        float2 z0 = __ldg((const float2*)(z + (size_t)e0 * 4) + 1);
        s0 += z0.x; s1 += z0.y;
    }
    float inv = 1.0f / (float)max(end - beg, 1);
    float2 zs = __ldg((const float2*)(z + (size_t)m * 4));
    out[(size_t)m * 2 + 0] = zs.x + (s0 + t0) * inv + __ldg(bf);
    out[(size_t)m * 2 + 1] = zs.y + (s1 + t1) * inv + __ldg(bf + 1);
}

// ---------------------------------------------------------------- launch
extern "C" void kernel_launch(void* const* d_in, const int* in_sizes, int n_in,
                              void* d_out, int out_size) {
    const float* features = (const float*)d_in[0];
    const int*   src      = (const int*)d_in[1];
    const int*   dst      = (const int*)d_in[2];
    const float* W1s      = (const float*)d_in[3];
    const float* W1n      = (const float*)d_in[4];
    const float* b1       = (const float*)d_in[5];
    const float* W2s      = (const float*)d_in[6];
    const float* W2n      = (const float*)d_in[7];
    const float* b2       = (const float*)d_in[8];
    const float* Wc       = (const float*)d_in[9];
    const float* bc       = (const float*)d_in[10];

    int N = in_sizes[0] / D;
    int E = in_sizes[1];

    int *cnt, *rowstart, *csrsrc, *bsum, *locoff;
    float *wfs, *wfn, *bf, *zbuf;
    __half *feat16, *agg16, *w16;
    cudaGetSymbolAddress((void**)&cnt, g_cnt);
    cudaGetSymbolAddress((void**)&rowstart, g_rowstart);
    cudaGetSymbolAddress((void**)&csrsrc, g_csrsrc);
    cudaGetSymbolAddress((void**)&bsum, g_bsum);
    cudaGetSymbolAddress((void**)&locoff, g_locoff);
    cudaGetSymbolAddress((void**)&wfs, g_wfs);
    cudaGetSymbolAddress((void**)&wfn, g_wfn);
    cudaGetSymbolAddress((void**)&bf, g_bf);
    cudaGetSymbolAddress((void**)&zbuf, g_z);
    cudaGetSymbolAddress((void**)&feat16, g_feat16);
    cudaGetSymbolAddress((void**)&agg16, g_agg16);
    cudaGetSymbolAddress((void**)&w16, g_w16);

    static cudaStream_t s1 = nullptr;
    static cudaEvent_t ev0 = nullptr, ev1 = nullptr;
    static int init_done = 0;
    if (!init_done) {
        cudaFuncSetAttribute(gemm_sage_f16,
                             cudaFuncAttributeMaxDynamicSharedMemorySize, 65536);
        if (cudaStreamCreateWithFlags(&s1, cudaStreamNonBlocking) != cudaSuccess) s1 = nullptr;
        if (s1) {
            cudaEventCreateWithFlags(&ev0, cudaEventDisableTiming);
            cudaEventCreateWithFlags(&ev1, cudaEventDisableTiming);
        }
        init_done = 1;
    }

    int mblocks = (N + 127) / 128;
    int gblocks = (N + 7) / 8;
    int n4 = N * (D / 4);
    int nb = (N + SCAN_B - 1) / SCAN_B;
    const int SMEM = 65536;

    // side stream: conversions + fused layer-2 weights (no CSR deps)
    cudaStream_t cs = s1 ? s1 : (cudaStream_t)0;
    if (s1) {
        cudaEventRecord(ev0, 0);
        cudaStreamWaitEvent(s1, ev0, 0);
    }
    conv16_kernel<<<(n4 + 255) / 256, 256, 0, cs>>>(features, feat16, n4);
    wconv_kernel<<<(2 * D * D + 255) / 256, 256, 0, cs>>>(W1s, W1n);
    wfuse_kernel<<<1, 512, 0, cs>>>(W2s, W2n, Wc, b2, bc);
    if (s1) cudaEventRecord(ev1, s1);

    // main stream: CSR build
    cudaMemsetAsync(cnt, 0, (size_t)N * sizeof(int));
    hist_kernel<<<(E / 2 + 255) / 256, 256>>>((const int2*)dst, cnt, (int2*)locoff, E / 2);
    scan_bsum_kernel<<<nb, SCAN_B>>>(cnt, bsum, N);
    scan_top_kernel<<<1, 512>>>(bsum, rowstart, nb, N);
    scan_fin_kernel<<<nb, SCAN_B>>>(cnt, bsum, rowstart, N);
    fill2_kernel<<<(E / 2 + 255) / 256, 256>>>((const int2*)src, (const int2*)dst,
                                               (const int2*)locoff, rowstart, csrsrc, E / 2);

    if (s1) cudaStreamWaitEvent((cudaStream_t)0, ev1, 0);  // join conversions

    gather16_kernel<<<gblocks, 256>>>(feat16, rowstart, csrsrc, agg16, N);
    gemm_sage_f16<<<mblocks, 256, SMEM>>>(feat16, agg16, w16, w16 + D * D,
                                          b1, N, wfs, wfn, zbuf);
    final_kernel<<<(N + 255) / 256, 256>>>(zbuf, rowstart, csrsrc, bf,
                                           (float*)d_out, N);
}

// round 16
// speedup vs baseline: 1.0258x; 1.0206x over previous
#include <cuda_runtime.h>
#include <cuda_fp16.h>
#include <cstdint>

#define N_NODES 100000
#define N_EDGES 1600000
#define D 128
#define SCAN_B 256

// Scratch (allocation-free: __device__ globals)
__device__ int    g_cnt[N_NODES];
__device__ int    g_cursor[N_NODES];
__device__ int    g_rowstart[N_NODES + 1];
__device__ int    g_bsum[1024];
__device__ int    g_csrsrc[N_EDGES];
__device__ float  g_wfs[D * 2];
__device__ float  g_wfn[D * 2];
__device__ float  g_bf[2];
__device__ __align__(16) float g_z[(size_t)N_NODES * 4];  // [self0,self1,neigh0,neigh1]
__device__ __align__(128) __half g_feat16[(size_t)N_NODES * D];
__device__ __align__(128) __half g_agg16[(size_t)N_NODES * D];
__device__ __align__(128) __half g_w16[2][D * D];  // W1s^T, W1n^T (n-major)

// ---------------------------------------------------------------- helpers
__device__ __forceinline__ void mma_f16(float* d, const uint32_t* a, const uint32_t* b) {
    asm volatile(
        "mma.sync.aligned.m16n8k16.row.col.f32.f16.f16.f32 "
        "{%0,%1,%2,%3}, {%4,%5,%6,%7}, {%8,%9}, {%0,%1,%2,%3};"
        : "+f"(d[0]), "+f"(d[1]), "+f"(d[2]), "+f"(d[3])
        : "r"(a[0]), "r"(a[1]), "r"(a[2]), "r"(a[3]), "r"(b[0]), "r"(b[1]));
}
__device__ __forceinline__ void cp16(uint32_t dst, const void* src) {
    asm volatile("cp.async.cg.shared.global [%0], [%1], 16;" :: "r"(dst), "l"(src));
}
#define CP_COMMIT() asm volatile("cp.async.commit_group;" ::: "memory")
#define CP_WAIT(n)  asm volatile("cp.async.wait_group %0;" :: "n"(n) : "memory")

// ---------------------------------------------------------------- conversions
__global__ void conv16_kernel(const float* __restrict__ in, __half* __restrict__ out, int n4) {
    int i = blockIdx.x * blockDim.x + threadIdx.x;
    if (i >= n4) return;
    float4 v = __ldg((const float4*)in + i);
    __half2 h0 = __floats2half2_rn(v.x, v.y);
    __half2 h1 = __floats2half2_rn(v.z, v.w);
    uint2 o;
    o.x = *(uint32_t*)&h0;
    o.y = *(uint32_t*)&h1;
    ((uint2*)out)[i] = o;
}

// transpose+convert layer-1 weights [k][n] fp32 -> [n][k] fp16
__global__ void wconv_kernel(const float* __restrict__ W1s, const float* __restrict__ W1n) {
    int t = blockIdx.x * blockDim.x + threadIdx.x;
    int m = t >> 14;
    int i = t & 16383;
    int n = i >> 7, k = i & 127;
    const float* W = (m == 0) ? W1s : W1n;
    g_w16[m][i] = __float2half_rn(__ldg(W + k * D + n));
}

// fused layer-2 weights: Wfs = W2s@Wc, Wfn = W2n@Wc, bf = b2@Wc + bc
__global__ void wfuse_kernel(const float* __restrict__ W2s, const float* __restrict__ W2n,
                             const float* __restrict__ Wc, const float* __restrict__ b2,
                             const float* __restrict__ bc) {
    int t = threadIdx.x;           // 512 threads, 1 block
    int which = t >> 8;
    int i = t & 255;
    int k = i >> 1, c = i & 1;
    const float* W = which ? W2n : W2s;
    float s = 0.f;
#pragma unroll 4
    for (int j = 0; j < D; j++) s += __ldg(W + k * D + j) * __ldg(Wc + j * 2 + c);
    if (which) g_wfn[i] = s; else g_wfs[i] = s;
    if (t < 2) {
        float sb = __ldg(bc + t);
        for (int j = 0; j < D; j++) sb += __ldg(b2 + j) * __ldg(Wc + j * 2 + t);
        g_bf[t] = sb;
    }
}

// ---------------------------------------------------------------- CSR build
__global__ void hist_kernel(const int2* __restrict__ dst2, int* __restrict__ cnt, int E2) {
    int i = blockIdx.x * blockDim.x + threadIdx.x;
    if (i < E2) {
        int2 d = __ldg(dst2 + i);
        atomicAdd(&cnt[d.x], 1);
        atomicAdd(&cnt[d.y], 1);
    }
}

__global__ void scan_bsum_kernel(const int* __restrict__ cnt, int* __restrict__ bsum, int n) {
    __shared__ int sh[SCAN_B];
    int i = blockIdx.x * SCAN_B + threadIdx.x;
    sh[threadIdx.x] = (i < n) ? cnt[i] : 0;
    __syncthreads();
#pragma unroll
    for (int off = SCAN_B / 2; off; off >>= 1) {
        if (threadIdx.x < off) sh[threadIdx.x] += sh[threadIdx.x + off];
        __syncthreads();
    }
    if (threadIdx.x == 0) bsum[blockIdx.x] = sh[0];
}

// merged top+fin: each block redundantly prefixes the block sums (nb reads, cheap),
// then does its local exclusive scan with the offset. One kernel instead of two.
__global__ void scan_fin_kernel(const int* __restrict__ cnt, const int* __restrict__ bsum,
                                int* __restrict__ rowstart, int* __restrict__ cursor,
                                int n, int nb) {
    __shared__ int sh[SCAN_B];
    __shared__ int s_pre[SCAN_B];
    __shared__ int s_all[SCAN_B];
    int tid = threadIdx.x;
    int bid = blockIdx.x;
    // prefix over block sums
    int accPre = 0, accAll = 0;
    for (int j = tid; j < nb; j += SCAN_B) {
        int v = __ldg(bsum + j);
        accAll += v;
        if (j < bid) accPre += v;
    }
    s_pre[tid] = accPre;
    s_all[tid] = accAll;
    __syncthreads();
#pragma unroll
    for (int off = SCAN_B / 2; off; off >>= 1) {
        if (tid < off) {
            s_pre[tid] += s_pre[tid + off];
            s_all[tid] += s_all[tid + off];
        }
        __syncthreads();
    }
    int blockOff = s_pre[0];
    if (bid == 0 && tid == 0) rowstart[n] = s_all[0];
    // local exclusive scan
    int i = bid * SCAN_B + tid;
    int v = (i < n) ? cnt[i] : 0;
    sh[tid] = v;
    __syncthreads();
#pragma unroll
    for (int off = 1; off < SCAN_B; off <<= 1) {
        int u = (tid >= off) ? sh[tid - off] : 0;
        __syncthreads();
        sh[tid] += u;
        __syncthreads();
    }
    if (i < n) {
        int ex = sh[tid] - v + blockOff;
        rowstart[i] = ex;
        cursor[i] = ex;
    }
}

__global__ void fill2_kernel(const int2* __restrict__ src2, const int2* __restrict__ dst2,
                             int* __restrict__ cursor, int* __restrict__ csrsrc, int E2) {
    int i = blockIdx.x * blockDim.x + threadIdx.x;
    if (i < E2) {
        int2 s = __ldg(src2 + i);
        int2 d = __ldg(dst2 + i);
        int p0 = atomicAdd(&cursor[d.x], 1);
        csrsrc[p0] = s.x;
        int p1 = atomicAdd(&cursor[d.y], 1);
        csrsrc[p1] = s.y;
    }
}

// ---------------------------------------------------------------- layer-1 gather
__global__ void gather16_kernel(const __half* __restrict__ H, const int* __restrict__ rowstart,
                                const int* __restrict__ csrsrc, __half* __restrict__ agg, int N) {
    int w = (blockIdx.x * blockDim.x + threadIdx.x) >> 5;
    int lane = threadIdx.x & 31;
    if (w >= N) return;
    int beg = __ldg(rowstart + w);
    int end = __ldg(rowstart + w + 1);
    float2 a0 = make_float2(0.f, 0.f), a1 = make_float2(0.f, 0.f);
    float2 b0 = make_float2(0.f, 0.f), b1 = make_float2(0.f, 0.f);
    float2 c0 = make_float2(0.f, 0.f), c1 = make_float2(0.f, 0.f);
    float2 d0 = make_float2(0.f, 0.f), d1 = make_float2(0.f, 0.f);
    int i = beg;
    for (; i + 3 < end; i += 4) {
        int e0 = __ldg(csrsrc + i);
        int e1 = __ldg(csrsrc + i + 1);
        int e2 = __ldg(csrsrc + i + 2);
        int e3 = __ldg(csrsrc + i + 3);
        uint2 v0 = __ldg((const uint2*)(H + (size_t)e0 * D) + lane);
        uint2 v1 = __ldg((const uint2*)(H + (size_t)e1 * D) + lane);
        uint2 v2 = __ldg((const uint2*)(H + (size_t)e2 * D) + lane);
        uint2 v3 = __ldg((const uint2*)(H + (size_t)e3 * D) + lane);
        float2 p, q;
        p = __half22float2(*(__half2*)&v0.x); q = __half22float2(*(__half2*)&v0.y);
        a0.x += p.x; a0.y += p.y; a1.x += q.x; a1.y += q.y;
        p = __half22float2(*(__half2*)&v1.x); q = __half22float2(*(__half2*)&v1.y);
        b0.x += p.x; b0.y += p.y; b1.x += q.x; b1.y += q.y;
        p = __half22float2(*(__half2*)&v2.x); q = __half22float2(*(__half2*)&v2.y);
        c0.x += p.x; c0.y += p.y; c1.x += q.x; c1.y += q.y;
        p = __half22float2(*(__half2*)&v3.x); q = __half22float2(*(__half2*)&v3.y);
        d0.x += p.x; d0.y += p.y; d1.x += q.x; d1.y += q.y;
    }
    for (; i < end; i++) {
        int e0 = __ldg(csrsrc + i);
        uint2 v0 = __ldg((const uint2*)(H + (size_t)e0 * D) + lane);
        float2 p = __half22float2(*(__half2*)&v0.x);
        float2 q = __half22float2(*(__half2*)&v0.y);
        a0.x += p.x; a0.y += p.y; a1.x += q.x; a1.y += q.y;
    }
    float inv = 1.0f / (float)max(end - beg, 1);
    __half2 o0 = __floats2half2_rn((a0.x + b0.x + c0.x + d0.x) * inv,
                                   (a0.y + b0.y + c0.y + d0.y) * inv);
    __half2 o1 = __floats2half2_rn((a1.x + b1.x + c1.x + d1.x) * inv,
                                   (a1.y + b1.y + c1.y + d1.y) * inv);
    uint2 o;
    o.x = *(uint32_t*)&o0;
    o.y = *(uint32_t*)&o1;
    *((uint2*)(agg + (size_t)w * D) + lane) = o;
}

// ---------------------------------------------------------------- layer-1 GEMM + z epilogue
// h = relu( feat @ W1s + agg @ W1n + b1 )  [fp32, registers only]
// z[r] = ( h@Wfs , h@Wfn ). h is never materialized.
#define CHUNK_WORDS (128 * 32)
__global__ void __launch_bounds__(256, 2)
gemm_sage_f16(const __half* __restrict__ Aself, const __half* __restrict__ Aagg,
              const __half* __restrict__ Wself, const __half* __restrict__ Wneigh,
              const float* __restrict__ bias, int M,
              const float* __restrict__ Wfs, const float* __restrict__ Wfn,
              float* __restrict__ z) {
    extern __shared__ __align__(16) uint32_t dyn[];
    uint32_t* Abuf[2] = {dyn, dyn + CHUNK_WORDS};
    uint32_t* Bbuf[2] = {dyn + 2 * CHUNK_WORDS, dyn + 3 * CHUNK_WORDS};
    __shared__ float s_z[2][128][4];

    int tid = threadIdx.x;
    int wid = tid >> 5;
    int lane = tid & 31;
    int wm = wid >> 1;
    int wn = wid & 1;
    int row0 = blockIdx.x * 128;

    const __half* Aarr[2] = {Aself, Aagg};
    const __half* Warr[2] = {Wself, Wneigh};

    float acc[2][8][4];
#pragma unroll
    for (int mt = 0; mt < 2; mt++)
#pragma unroll
        for (int nt = 0; nt < 8; nt++)
#pragma unroll
            for (int e = 0; e < 4; e++) acc[mt][nt][e] = 0.f;

    int s_r = tid >> 3;
    int s_v = tid & 7;
    uint32_t a_sm[2], b_sm[2];
#pragma unroll
    for (int b = 0; b < 2; b++) {
        a_sm[b] = (uint32_t)__cvta_generic_to_shared(Abuf[b]);
        b_sm[b] = (uint32_t)__cvta_generic_to_shared(Bbuf[b]);
    }

    int r0l = wm * 32 + (lane >> 2);
    int wlo = lane & 3;
    int n_row = wn * 64 + (lane >> 2);

    {
#pragma unroll
        for (int it = 0; it < 4; it++) {
            int r = s_r + it * 32;
            int gr = min(row0 + r, M - 1);
            uint32_t off = (uint32_t)((r * 8 + (s_v ^ (r & 7))) * 16);
            cp16(a_sm[0] + off, Aarr[0] + (size_t)gr * D + s_v * 8);
            cp16(b_sm[0] + off, Warr[0] + (size_t)r * D + s_v * 8);
        }
        CP_COMMIT();
    }

#pragma unroll 1
    for (int step = 0; step < 4; ++step) {
        if (step < 3) {
            int ns = step + 1;
            const __half* A = Aarr[ns >> 1];
            const __half* W = Warr[ns >> 1];
            int k0 = (ns & 1) * 64;
            int nb = ns & 1;
#pragma unroll
            for (int it = 0; it < 4; it++) {
                int r = s_r + it * 32;
                int gr = min(row0 + r, M - 1);
                uint32_t off = (uint32_t)((r * 8 + (s_v ^ (r & 7))) * 16);
                cp16(a_sm[nb] + off, A + (size_t)gr * D + k0 + s_v * 8);
                cp16(b_sm[nb] + off, W + (size_t)r * D + k0 + s_v * 8);
            }
            CP_COMMIT();
            CP_WAIT(1);
        } else {
            CP_WAIT(0);
        }
        __syncthreads();

        const uint32_t* As = Abuf[step & 1];
        const uint32_t* Bs = Bbuf[step & 1];
#pragma unroll
        for (int ks = 0; ks < 2; ks++) { }  // (placeholder removed below)
#pragma unroll
        for (int ks = 0; ks < 4; ks++) {
            uint32_t af[2][4];
#pragma unroll
            for (int mt = 0; mt < 2; mt++) {
                int r = r0l + mt * 16;
                int sw = r & 7;
                int v0 = (2 * ks) ^ sw, v1 = (2 * ks + 1) ^ sw;
                af[mt][0] = As[r * 32 + v0 * 4 + wlo];
                af[mt][1] = As[(r + 8) * 32 + v0 * 4 + wlo];
                af[mt][2] = As[r * 32 + v1 * 4 + wlo];
                af[mt][3] = As[(r + 8) * 32 + v1 * 4 + wlo];
            }
#pragma unroll
            for (int nt = 0; nt < 8; nt++) {
                int n = n_row + nt * 8;
                int swn = n & 7;
                uint32_t b2[2];
                b2[0] = Bs[n * 32 + ((2 * ks) ^ swn) * 4 + wlo];
                b2[1] = Bs[n * 32 + ((2 * ks + 1) ^ swn) * 4 + wlo];
#pragma unroll
                for (int mt = 0; mt < 2; mt++)
                    mma_f16(acc[mt][nt], af[mt], b2);
            }
        }
        __syncthreads();
    }

    // ---- z epilogue ----
#pragma unroll
    for (int mt = 0; mt < 2; mt++) {
        float zsl0 = 0.f, zsl1 = 0.f, znl0 = 0.f, znl1 = 0.f;
        float zsh0 = 0.f, zsh1 = 0.f, znh0 = 0.f, znh1 = 0.f;
#pragma unroll
        for (int nt = 0; nt < 8; nt++) {
            int c = wn * 64 + nt * 8 + (lane & 3) * 2;
            float b0 = __ldg(bias + c), b1 = __ldg(bias + c + 1);
            float2 ws0 = __ldg((const float2*)(Wfs + (size_t)c * 2));
            float2 ws1 = __ldg((const float2*)(Wfs + (size_t)(c + 1) * 2));
            float2 wn0 = __ldg((const float2*)(Wfn + (size_t)c * 2));
            float2 wn1 = __ldg((const float2*)(Wfn + (size_t)(c + 1) * 2));
            float h0 = fmaxf(acc[mt][nt][0] + b0, 0.f);
            float h1 = fmaxf(acc[mt][nt][1] + b1, 0.f);
            float h2 = fmaxf(acc[mt][nt][2] + b0, 0.f);
            float h3 = fmaxf(acc[mt][nt][3] + b1, 0.f);
            zsl0 += h0 * ws0.x + h1 * ws1.x;  zsl1 += h0 * ws0.y + h1 * ws1.y;
            znl0 += h0 * wn0.x + h1 * wn1.x;  znl1 += h0 * wn0.y + h1 * wn1.y;
            zsh0 += h2 * ws0.x + h3 * ws1.x;  zsh1 += h2 * ws0.y + h3 * ws1.y;
            znh0 += h2 * wn0.x + h3 * wn1.x;  znh1 += h2 * wn0.y + h3 * wn1.y;
        }
#pragma unroll
        for (int off = 1; off <= 2; off <<= 1) {
            zsl0 += __shfl_xor_sync(0xFFFFFFFFu, zsl0, off);
            zsl1 += __shfl_xor_sync(0xFFFFFFFFu, zsl1, off);
            znl0 += __shfl_xor_sync(0xFFFFFFFFu, znl0, off);
            znl1 += __shfl_xor_sync(0xFFFFFFFFu, znl1, off);
            zsh0 += __shfl_xor_sync(0xFFFFFFFFu, zsh0, off);
            zsh1 += __shfl_xor_sync(0xFFFFFFFFu, zsh1, off);
            znh0 += __shfl_xor_sync(0xFFFFFFFFu, znh0, off);
            znh1 += __shfl_xor_sync(0xFFFFFFFFu, znh1, off);
        }
        if ((lane & 3) == 0) {
            int lr = wm * 32 + mt * 16 + (lane >> 2);
            s_z[wn][lr][0] = zsl0; s_z[wn][lr][1] = zsl1;
            s_z[wn][lr][2] = znl0; s_z[wn][lr][3] = znl1;
            s_z[wn][lr + 8][0] = zsh0; s_z[wn][lr + 8][1] = zsh1;
            s_z[wn][lr + 8][2] = znh0; s_z[wn][lr + 8][3] = znh1;
        }
    }
    __syncthreads();
    {
        int row = tid >> 1;
        int j = tid & 1;
        if (row0 + row < M) {
            float2 v;
            v.x = s_z[0][row][j * 2 + 0] + s_z[1][row][j * 2 + 0];
            v.y = s_z[0][row][j * 2 + 1] + s_z[1][row][j * 2 + 1];
            *(float2*)(z + (size_t)(row0 + row) * 4 + j * 2) = v;
        }
    }
}

// ---------------------------------------------------------------- final: 8-byte edge gather (4-way MLP)
__global__ void final_kernel(const float* __restrict__ z, const int* __restrict__ rowstart,
                             const int* __restrict__ csrsrc, const float* __restrict__ bf,
                             float* __restrict__ out, int N) {
    int m = blockIdx.x * blockDim.x + threadIdx.x;
    if (m >= N) return;
    int beg = __ldg(rowstart + m);
    int end = __ldg(rowstart + m + 1);
    float s0 = 0.f, s1 = 0.f, t0 = 0.f, t1 = 0.f;
    float u0 = 0.f, u1 = 0.f, v0a = 0.f, v1a = 0.f;
    int i = beg;
    for (; i + 3 < end; i += 4) {
        int e0 = __ldg(csrsrc + i);
        int e1 = __ldg(csrsrc + i + 1);
        int e2 = __ldg(csrsrc + i + 2);
        int e3 = __ldg(csrsrc + i + 3);
        float2 z0 = __ldg((const float2*)(z + (size_t)e0 * 4) + 1);
        float2 z1 = __ldg((const float2*)(z + (size_t)e1 * 4) + 1);
        float2 z2 = __ldg((const float2*)(z + (size_t)e2 * 4) + 1);
        float2 z3 = __ldg((const float2*)(z + (size_t)e3 * 4) + 1);
        s0 += z0.x; s1 += z0.y;
        t0 += z1.x; t1 += z1.y;
        u0 += z2.x; u1 += z2.y;
        v0a += z3.x; v1a += z3.y;
    }
    for (; i < end; i++) {
        int e0 = __ldg(csrsrc + i);
        float2 z0 = __ldg((const float2*)(z + (size_t)e0 * 4) + 1);
        s0 += z0.x; s1 += z0.y;
    }
    float inv = 1.0f / (float)max(end - beg, 1);
    float2 zs = __ldg((const float2*)(z + (size_t)m * 4));
    out[(size_t)m * 2 + 0] = zs.x + (s0 + t0 + u0 + v0a) * inv + __ldg(bf);
    out[(size_t)m * 2 + 1] = zs.y + (s1 + t1 + u1 + v1a) * inv + __ldg(bf + 1);
}

// ---------------------------------------------------------------- launch
extern "C" void kernel_launch(void* const* d_in, const int* in_sizes, int n_in,
                              void* d_out, int out_size) {
    const float* features = (const float*)d_in[0];
    const int*   src      = (const int*)d_in[1];
    const int*   dst      = (const int*)d_in[2];
    const float* W1s      = (const float*)d_in[3];
    const float* W1n      = (const float*)d_in[4];
    const float* b1       = (const float*)d_in[5];
    const float* W2s      = (const float*)d_in[6];
    const float* W2n      = (const float*)d_in[7];
    const float* b2       = (const float*)d_in[8];
    const float* Wc       = (const float*)d_in[9];
    const float* bc       = (const float*)d_in[10];

    int N = in_sizes[0] / D;
    int E = in_sizes[1];

    int *cnt, *cursor, *rowstart, *csrsrc, *bsum;
    float *wfs, *wfn, *bf, *zbuf;
    __half *feat16, *agg16, *w16;
    cudaGetSymbolAddress((void**)&cnt, g_cnt);
    cudaGetSymbolAddress((void**)&cursor, g_cursor);
    cudaGetSymbolAddress((void**)&rowstart, g_rowstart);
    cudaGetSymbolAddress((void**)&csrsrc, g_csrsrc);
    cudaGetSymbolAddress((void**)&bsum, g_bsum);
    cudaGetSymbolAddress((void**)&wfs, g_wfs);
    cudaGetSymbolAddress((void**)&wfn, g_wfn);
    cudaGetSymbolAddress((void**)&bf, g_bf);
    cudaGetSymbolAddress((void**)&zbuf, g_z);
    cudaGetSymbolAddress((void**)&feat16, g_feat16);
    cudaGetSymbolAddress((void**)&agg16, g_agg16);
    cudaGetSymbolAddress((void**)&w16, g_w16);

    static cudaStream_t s1 = nullptr;
    static cudaEvent_t ev0 = nullptr, ev1 = nullptr;
    static int init_done = 0;
    if (!init_done) {
        cudaFuncSetAttribute(gemm_sage_f16,
                             cudaFuncAttributeMaxDynamicSharedMemorySize, 65536);
        if (cudaStreamCreateWithFlags(&s1, cudaStreamNonBlocking) != cudaSuccess) s1 = nullptr;
        if (s1) {
            cudaEventCreateWithFlags(&ev0, cudaEventDisableTiming);
            cudaEventCreateWithFlags(&ev1, cudaEventDisableTiming);
        }
        init_done = 1;
    }

    int mblocks = (N + 127) / 128;
    int gblocks = (N + 7) / 8;
    int n4 = N * (D / 4);
    int nb = (N + SCAN_B - 1) / SCAN_B;
    const int SMEM = 65536;

    // side stream: conversions + fused layer-2 weights (no CSR deps)
    cudaStream_t cs = s1 ? s1 : (cudaStream_t)0;
    if (s1) {
        cudaEventRecord(ev0, 0);
        cudaStreamWaitEvent(s1, ev0, 0);
    }
    conv16_kernel<<<(n4 + 255) / 256, 256, 0, cs>>>(features, feat16, n4);
    wconv_kernel<<<(2 * D * D + 255) / 256, 256, 0, cs>>>(W1s, W1n);
    wfuse_kernel<<<1, 512, 0, cs>>>(W2s, W2n, Wc, b2, bc);
    if (s1) cudaEventRecord(ev1, s1);

    // main stream: CSR build (round-12 proven hist/fill + merged scan)
    cudaMemsetAsync(cnt, 0, (size_t)N * sizeof(int));
    hist_kernel<<<(E / 2 + 255) / 256, 256>>>((const int2*)dst, cnt, E / 2);
    scan_bsum_kernel<<<nb, SCAN_B>>>(cnt, bsum, N);
    scan_fin_kernel<<<nb, SCAN_B>>>(cnt, bsum, rowstart, cursor, N, nb);
    fill2_kernel<<<(E / 2 + 255) / 256, 256>>>((const int2*)src, (const int2*)dst,
                                               cursor, csrsrc, E / 2);

    if (s1) cudaStreamWaitEvent((cudaStream_t)0, ev1, 0);  // join conversions

    gather16_kernel<<<gblocks, 256>>>(feat16, rowstart, csrsrc, agg16, N);
    gemm_sage_f16<<<mblocks, 256, SMEM>>>(feat16, agg16, w16, w16 + D * D,
                                          b1, N, wfs, wfn, zbuf);
    final_kernel<<<(N + 255) / 256, 256>>>(zbuf, rowstart, csrsrc, bf,
                                           (float*)d_out, N);
}

// round 17
// speedup vs baseline: 1.0834x; 1.0561x over previous
#include <cuda_runtime.h>
#include <cuda_fp16.h>
#include <cstdint>

#define N_NODES 100000
#define N_EDGES 1600000
#define D 128
#define SCAN_B 256

// Scratch (allocation-free: __device__ globals)
__device__ int    g_cnt[N_NODES];
__device__ int    g_cursor[N_NODES];
__device__ int    g_rowstart[N_NODES + 1];
__device__ int    g_bsum[1024];
__device__ int    g_csrsrc[N_EDGES];
__device__ float  g_wfs[D * 2];
__device__ float  g_wfn[D * 2];
__device__ float  g_bf[2];
__device__ __align__(16) float g_z[(size_t)N_NODES * 4];  // [self0,self1,neigh0,neigh1]
__device__ __align__(128) __half g_feat16[(size_t)N_NODES * D];
__device__ __align__(128) __half g_agg16[(size_t)N_NODES * D];
__device__ __align__(128) __half g_w16[2][D * D];  // W1s^T, W1n^T (n-major)

// ---------------------------------------------------------------- helpers
__device__ __forceinline__ void mma_f16(float* d, const uint32_t* a, const uint32_t* b) {
    asm volatile(
        "mma.sync.aligned.m16n8k16.row.col.f32.f16.f16.f32 "
        "{%0,%1,%2,%3}, {%4,%5,%6,%7}, {%8,%9}, {%0,%1,%2,%3};"
        : "+f"(d[0]), "+f"(d[1]), "+f"(d[2]), "+f"(d[3])
        : "r"(a[0]), "r"(a[1]), "r"(a[2]), "r"(a[3]), "r"(b[0]), "r"(b[1]));
}
__device__ __forceinline__ void cp16(uint32_t dst, const void* src) {
    asm volatile("cp.async.cg.shared.global [%0], [%1], 16;" :: "r"(dst), "l"(src));
}
#define CP_COMMIT() asm volatile("cp.async.commit_group;" ::: "memory")
#define CP_WAIT(n)  asm volatile("cp.async.wait_group %0;" :: "n"(n) : "memory")

// ---------------------------------------------------------------- conversions
__global__ void conv16_kernel(const float* __restrict__ in, __half* __restrict__ out, int n4) {
    int i = blockIdx.x * blockDim.x + threadIdx.x;
    if (i >= n4) return;
    float4 v = __ldg((const float4*)in + i);
    __half2 h0 = __floats2half2_rn(v.x, v.y);
    __half2 h1 = __floats2half2_rn(v.z, v.w);
    uint2 o;
    o.x = *(uint32_t*)&h0;
    o.y = *(uint32_t*)&h1;
    ((uint2*)out)[i] = o;
}

// transpose+convert layer-1 weights [k][n] fp32 -> [n][k] fp16
__global__ void wconv_kernel(const float* __restrict__ W1s, const float* __restrict__ W1n) {
    int t = blockIdx.x * blockDim.x + threadIdx.x;
    int m = t >> 14;
    int i = t & 16383;
    int n = i >> 7, k = i & 127;
    const float* W = (m == 0) ? W1s : W1n;
    g_w16[m][i] = __float2half_rn(__ldg(W + k * D + n));
}

// fused layer-2 weights: Wfs = W2s@Wc, Wfn = W2n@Wc, bf = b2@Wc + bc
__global__ void wfuse_kernel(const float* __restrict__ W2s, const float* __restrict__ W2n,
                             const float* __restrict__ Wc, const float* __restrict__ b2,
                             const float* __restrict__ bc) {
    int t = threadIdx.x;           // 512 threads, 1 block
    int which = t >> 8;
    int i = t & 255;
    int k = i >> 1, c = i & 1;
    const float* W = which ? W2n : W2s;
    float s = 0.f;
#pragma unroll 4
    for (int j = 0; j < D; j++) s += __ldg(W + k * D + j) * __ldg(Wc + j * 2 + c);
    if (which) g_wfn[i] = s; else g_wfs[i] = s;
    if (t < 2) {
        float sb = __ldg(bc + t);
        for (int j = 0; j < D; j++) sb += __ldg(b2 + j) * __ldg(Wc + j * 2 + t);
        g_bf[t] = sb;
    }
}

// ---------------------------------------------------------------- CSR build
__global__ void hist_kernel(const int2* __restrict__ dst2, int* __restrict__ cnt, int E2) {
    int i = blockIdx.x * blockDim.x + threadIdx.x;
    if (i < E2) {
        int2 d = __ldg(dst2 + i);
        atomicAdd(&cnt[d.x], 1);
        atomicAdd(&cnt[d.y], 1);
    }
}

__global__ void scan_bsum_kernel(const int* __restrict__ cnt, int* __restrict__ bsum, int n) {
    __shared__ int sh[SCAN_B];
    int i = blockIdx.x * SCAN_B + threadIdx.x;
    sh[threadIdx.x] = (i < n) ? cnt[i] : 0;
    __syncthreads();
#pragma unroll
    for (int off = SCAN_B / 2; off; off >>= 1) {
        if (threadIdx.x < off) sh[threadIdx.x] += sh[threadIdx.x + off];
        __syncthreads();
    }
    if (threadIdx.x == 0) bsum[blockIdx.x] = sh[0];
}

// merged top+fin: each block redundantly prefixes the block sums, then local scan.
__global__ void scan_fin_kernel(const int* __restrict__ cnt, const int* __restrict__ bsum,
                                int* __restrict__ rowstart, int* __restrict__ cursor,
                                int n, int nb) {
    __shared__ int sh[SCAN_B];
    __shared__ int s_pre[SCAN_B];
    __shared__ int s_all[SCAN_B];
    int tid = threadIdx.x;
    int bid = blockIdx.x;
    int accPre = 0, accAll = 0;
    for (int j = tid; j < nb; j += SCAN_B) {
        int v = __ldg(bsum + j);
        accAll += v;
        if (j < bid) accPre += v;
    }
    s_pre[tid] = accPre;
    s_all[tid] = accAll;
    __syncthreads();
#pragma unroll
    for (int off = SCAN_B / 2; off; off >>= 1) {
        if (tid < off) {
            s_pre[tid] += s_pre[tid + off];
            s_all[tid] += s_all[tid + off];
        }
        __syncthreads();
    }
    int blockOff = s_pre[0];
    if (bid == 0 && tid == 0) rowstart[n] = s_all[0];
    int i = bid * SCAN_B + tid;
    int v = (i < n) ? cnt[i] : 0;
    sh[tid] = v;
    __syncthreads();
#pragma unroll
    for (int off = 1; off < SCAN_B; off <<= 1) {
        int u = (tid >= off) ? sh[tid - off] : 0;
        __syncthreads();
        sh[tid] += u;
        __syncthreads();
    }
    if (i < n) {
        int ex = sh[tid] - v + blockOff;
        rowstart[i] = ex;
        cursor[i] = ex;
    }
}

__global__ void fill2_kernel(const int2* __restrict__ src2, const int2* __restrict__ dst2,
                             int* __restrict__ cursor, int* __restrict__ csrsrc, int E2) {
    int i = blockIdx.x * blockDim.x + threadIdx.x;
    if (i < E2) {
        int2 s = __ldg(src2 + i);
        int2 d = __ldg(dst2 + i);
        int p0 = atomicAdd(&cursor[d.x], 1);
        csrsrc[p0] = s.x;
        int p1 = atomicAdd(&cursor[d.y], 1);
        csrsrc[p1] = s.y;
    }
}

// ---------------------------------------------------------------- layer-1 gather (8-way MLP)
__global__ void gather16_kernel(const __half* __restrict__ H, const int* __restrict__ rowstart,
                                const int* __restrict__ csrsrc, __half* __restrict__ agg, int N) {
    int w = (blockIdx.x * blockDim.x + threadIdx.x) >> 5;
    int lane = threadIdx.x & 31;
    if (w >= N) return;
    int beg = __ldg(rowstart + w);
    int end = __ldg(rowstart + w + 1);
    float2 acc0[4], acc1[4];
#pragma unroll
    for (int j = 0; j < 4; j++) {
        acc0[j] = make_float2(0.f, 0.f);
        acc1[j] = make_float2(0.f, 0.f);
    }
    int i = beg;
    for (; i + 7 < end; i += 8) {
        int e[8];
#pragma unroll
        for (int j = 0; j < 8; j++) e[j] = __ldg(csrsrc + i + j);
        uint2 v[8];
#pragma unroll
        for (int j = 0; j < 8; j++)
            v[j] = __ldg((const uint2*)(H + (size_t)e[j] * D) + lane);
#pragma unroll
        for (int j = 0; j < 8; j++) {
            float2 p = __half22float2(*(__half2*)&v[j].x);
            float2 q = __half22float2(*(__half2*)&v[j].y);
            acc0[j & 3].x += p.x; acc0[j & 3].y += p.y;
            acc1[j & 3].x += q.x; acc1[j & 3].y += q.y;
        }
    }
    for (; i + 3 < end; i += 4) {
        int e[4];
#pragma unroll
        for (int j = 0; j < 4; j++) e[j] = __ldg(csrsrc + i + j);
        uint2 v[4];
#pragma unroll
        for (int j = 0; j < 4; j++)
            v[j] = __ldg((const uint2*)(H + (size_t)e[j] * D) + lane);
#pragma unroll
        for (int j = 0; j < 4; j++) {
            float2 p = __half22float2(*(__half2*)&v[j].x);
            float2 q = __half22float2(*(__half2*)&v[j].y);
            acc0[j].x += p.x; acc0[j].y += p.y;
            acc1[j].x += q.x; acc1[j].y += q.y;
        }
    }
    for (; i < end; i++) {
        int e0 = __ldg(csrsrc + i);
        uint2 v0 = __ldg((const uint2*)(H + (size_t)e0 * D) + lane);
        float2 p = __half22float2(*(__half2*)&v0.x);
        float2 q = __half22float2(*(__half2*)&v0.y);
        acc0[0].x += p.x; acc0[0].y += p.y;
        acc1[0].x += q.x; acc1[0].y += q.y;
    }
    float inv = 1.0f / (float)max(end - beg, 1);
    float s0x = (acc0[0].x + acc0[1].x) + (acc0[2].x + acc0[3].x);
    float s0y = (acc0[0].y + acc0[1].y) + (acc0[2].y + acc0[3].y);
    float s1x = (acc1[0].x + acc1[1].x) + (acc1[2].x + acc1[3].x);
    float s1y = (acc1[0].y + acc1[1].y) + (acc1[2].y + acc1[3].y);
    __half2 o0 = __floats2half2_rn(s0x * inv, s0y * inv);
    __half2 o1 = __floats2half2_rn(s1x * inv, s1y * inv);
    uint2 o;
    o.x = *(uint32_t*)&o0;
    o.y = *(uint32_t*)&o1;
    *((uint2*)(agg + (size_t)w * D) + lane) = o;
}

// ---------------------------------------------------------------- layer-1 GEMM + z epilogue
// h = relu( feat @ W1s + agg @ W1n + b1 )  [fp32, registers only]
// z[r] = ( h@Wfs , h@Wfn ). h is never materialized.
#define CHUNK_WORDS (128 * 32)
__global__ void __launch_bounds__(256, 2)
gemm_sage_f16(const __half* __restrict__ Aself, const __half* __restrict__ Aagg,
              const __half* __restrict__ Wself, const __half* __restrict__ Wneigh,
              const float* __restrict__ bias, int M,
              const float* __restrict__ Wfs, const float* __restrict__ Wfn,
              float* __restrict__ z) {
    extern __shared__ __align__(16) uint32_t dyn[];
    uint32_t* Abuf[2] = {dyn, dyn + CHUNK_WORDS};
    uint32_t* Bbuf[2] = {dyn + 2 * CHUNK_WORDS, dyn + 3 * CHUNK_WORDS};
    __shared__ float s_z[2][128][4];

    int tid = threadIdx.x;
    int wid = tid >> 5;
    int lane = tid & 31;
    int wm = wid >> 1;
    int wn = wid & 1;
    int row0 = blockIdx.x * 128;

    const __half* Aarr[2] = {Aself, Aagg};
    const __half* Warr[2] = {Wself, Wneigh};

    float acc[2][8][4];
#pragma unroll
    for (int mt = 0; mt < 2; mt++)
#pragma unroll
        for (int nt = 0; nt < 8; nt++)
#pragma unroll
            for (int e = 0; e < 4; e++) acc[mt][nt][e] = 0.f;

    int s_r = tid >> 3;
    int s_v = tid & 7;
    uint32_t a_sm[2], b_sm[2];
#pragma unroll
    for (int b = 0; b < 2; b++) {
        a_sm[b] = (uint32_t)__cvta_generic_to_shared(Abuf[b]);
        b_sm[b] = (uint32_t)__cvta_generic_to_shared(Bbuf[b]);
    }

    int r0l = wm * 32 + (lane >> 2);
    int wlo = lane & 3;
    int n_row = wn * 64 + (lane >> 2);

    {
#pragma unroll
        for (int it = 0; it < 4; it++) {
            int r = s_r + it * 32;
            int gr = min(row0 + r, M - 1);
            uint32_t off = (uint32_t)((r * 8 + (s_v ^ (r & 7))) * 16);
            cp16(a_sm[0] + off, Aarr[0] + (size_t)gr * D + s_v * 8);
            cp16(b_sm[0] + off, Warr[0] + (size_t)r * D + s_v * 8);
        }
        CP_COMMIT();
    }

#pragma unroll 1
    for (int step = 0; step < 4; ++step) {
        if (step < 3) {
            int ns = step + 1;
            const __half* A = Aarr[ns >> 1];
            const __half* W = Warr[ns >> 1];
            int k0 = (ns & 1) * 64;
            int nb = ns & 1;
#pragma unroll
            for (int it = 0; it < 4; it++) {
                int r = s_r + it * 32;
                int gr = min(row0 + r, M - 1);
                uint32_t off = (uint32_t)((r * 8 + (s_v ^ (r & 7))) * 16);
                cp16(a_sm[nb] + off, A + (size_t)gr * D + k0 + s_v * 8);
                cp16(b_sm[nb] + off, W + (size_t)r * D + k0 + s_v * 8);
            }
            CP_COMMIT();
            CP_WAIT(1);
        } else {
            CP_WAIT(0);
        }
        __syncthreads();

        const uint32_t* As = Abuf[step & 1];
        const uint32_t* Bs = Bbuf[step & 1];
#pragma unroll
        for (int ks = 0; ks < 4; ks++) {
            uint32_t af[2][4];
#pragma unroll
            for (int mt = 0; mt < 2; mt++) {
                int r = r0l + mt * 16;
                int sw = r & 7;
                int v0 = (2 * ks) ^ sw, v1 = (2 * ks + 1) ^ sw;
                af[mt][0] = As[r * 32 + v0 * 4 + wlo];
                af[mt][1] = As[(r + 8) * 32 + v0 * 4 + wlo];
                af[mt][2] = As[r * 32 + v1 * 4 + wlo];
                af[mt][3] = As[(r + 8) * 32 + v1 * 4 + wlo];
            }
#pragma unroll
            for (int nt = 0; nt < 8; nt++) {
                int n = n_row + nt * 8;
                int swn = n & 7;
                uint32_t b2[2];
                b2[0] = Bs[n * 32 + ((2 * ks) ^ swn) * 4 + wlo];
                b2[1] = Bs[n * 32 + ((2 * ks + 1) ^ swn) * 4 + wlo];
#pragma unroll
                for (int mt = 0; mt < 2; mt++)
                    mma_f16(acc[mt][nt], af[mt], b2);
            }
        }
        __syncthreads();
    }

    // ---- z epilogue ----
#pragma unroll
    for (int mt = 0; mt < 2; mt++) {
        float zsl0 = 0.f, zsl1 = 0.f, znl0 = 0.f, znl1 = 0.f;
        float zsh0 = 0.f, zsh1 = 0.f, znh0 = 0.f, znh1 = 0.f;
#pragma unroll
        for (int nt = 0; nt < 8; nt++) {
            int c = wn * 64 + nt * 8 + (lane & 3) * 2;
            float b0 = __ldg(bias + c), b1 = __ldg(bias + c + 1);
            float2 ws0 = __ldg((const float2*)(Wfs + (size_t)c * 2));
            float2 ws1 = __ldg((const float2*)(Wfs + (size_t)(c + 1) * 2));
            float2 wn0 = __ldg((const float2*)(Wfn + (size_t)c * 2));
            float2 wn1 = __ldg((const float2*)(Wfn + (size_t)(c + 1) * 2));
            float h0 = fmaxf(acc[mt][nt][0] + b0, 0.f);
            float h1 = fmaxf(acc[mt][nt][1] + b1, 0.f);
            float h2 = fmaxf(acc[mt][nt][2] + b0, 0.f);
            float h3 = fmaxf(acc[mt][nt][3] + b1, 0.f);
            zsl0 += h0 * ws0.x + h1 * ws1.x;  zsl1 += h0 * ws0.y + h1 * ws1.y;
            znl0 += h0 * wn0.x + h1 * wn1.x;  znl1 += h0 * wn0.y + h1 * wn1.y;
            zsh0 += h2 * ws0.x + h3 * ws1.x;  zsh1 += h2 * ws0.y + h3 * ws1.y;
            znh0 += h2 * wn0.x + h3 * wn1.x;  znh1 += h2 * wn0.y + h3 * wn1.y;
        }
#pragma unroll
        for (int off = 1; off <= 2; off <<= 1) {
            zsl0 += __shfl_xor_sync(0xFFFFFFFFu, zsl0, off);
            zsl1 += __shfl_xor_sync(0xFFFFFFFFu, zsl1, off);
            znl0 += __shfl_xor_sync(0xFFFFFFFFu, znl0, off);
            znl1 += __shfl_xor_sync(0xFFFFFFFFu, znl1, off);
            zsh0 += __shfl_xor_sync(0xFFFFFFFFu, zsh0, off);
            zsh1 += __shfl_xor_sync(0xFFFFFFFFu, zsh1, off);
            znh0 += __shfl_xor_sync(0xFFFFFFFFu, znh0, off);
            znh1 += __shfl_xor_sync(0xFFFFFFFFu, znh1, off);
        }
        if ((lane & 3) == 0) {
            int lr = wm * 32 + mt * 16 + (lane >> 2);
            s_z[wn][lr][0] = zsl0; s_z[wn][lr][1] = zsl1;
            s_z[wn][lr][2] = znl0; s_z[wn][lr][3] = znl1;
            s_z[wn][lr + 8][0] = zsh0; s_z[wn][lr + 8][1] = zsh1;
            s_z[wn][lr + 8][2] = znh0; s_z[wn][lr + 8][3] = znh1;
        }
    }
    __syncthreads();
    {
        int row = tid >> 1;
        int j = tid & 1;
        if (row0 + row < M) {
            float2 v;
            v.x = s_z[0][row][j * 2 + 0] + s_z[1][row][j * 2 + 0];
            v.y = s_z[0][row][j * 2 + 1] + s_z[1][row][j * 2 + 1];
            *(float2*)(z + (size_t)(row0 + row) * 4 + j * 2) = v;
        }
    }
}

// ---------------------------------------------------------------- final: 8-byte edge gather (4-way MLP)
__global__ void final_kernel(const float* __restrict__ z, const int* __restrict__ rowstart,
                             const int* __restrict__ csrsrc, const float* __restrict__ bf,
                             float* __restrict__ out, int N) {
    int m = blockIdx.x * blockDim.x + threadIdx.x;
    if (m >= N) return;
    int beg = __ldg(rowstart + m);
    int end = __ldg(rowstart + m + 1);
    float s0 = 0.f, s1 = 0.f, t0 = 0.f, t1 = 0.f;
    float u0 = 0.f, u1 = 0.f, v0a = 0.f, v1a = 0.f;
    int i = beg;
    for (; i + 3 < end; i += 4) {
        int e0 = __ldg(csrsrc + i);
        int e1 = __ldg(csrsrc + i + 1);
        int e2 = __ldg(csrsrc + i + 2);
        int e3 = __ldg(csrsrc + i + 3);
        float2 z0 = __ldg((const float2*)(z + (size_t)e0 * 4) + 1);
        float2 z1 = __ldg((const float2*)(z + (size_t)e1 * 4) + 1);
        float2 z2 = __ldg((const float2*)(z + (size_t)e2 * 4) + 1);
        float2 z3 = __ldg((const float2*)(z + (size_t)e3 * 4) + 1);
        s0 += z0.x; s1 += z0.y;
        t0 += z1.x; t1 += z1.y;
        u0 += z2.x; u1 += z2.y;
        v0a += z3.x; v1a += z3.y;
    }
    for (; i < end; i++) {
        int e0 = __ldg(csrsrc + i);
        float2 z0 = __ldg((const float2*)(z + (size_t)e0 * 4) + 1);
        s0 += z0.x; s1 += z0.y;
    }
    float inv = 1.0f / (float)max(end - beg, 1);
    float2 zs = __ldg((const float2*)(z + (size_t)m * 4));
    out[(size_t)m * 2 + 0] = zs.x + (s0 + t0 + u0 + v0a) * inv + __ldg(bf);
    out[(size_t)m * 2 + 1] = zs.y + (s1 + t1 + u1 + v1a) * inv + __ldg(bf + 1);
}

// ---------------------------------------------------------------- launch
extern "C" void kernel_launch(void* const* d_in, const int* in_sizes, int n_in,
                              void* d_out, int out_size) {
    const float* features = (const float*)d_in[0];
    const int*   src      = (const int*)d_in[1];
    const int*   dst      = (const int*)d_in[2];
    const float* W1s      = (const float*)d_in[3];
    const float* W1n      = (const float*)d_in[4];
    const float* b1       = (const float*)d_in[5];
    const float* W2s      = (const float*)d_in[6];
    const float* W2n      = (const float*)d_in[7];
    const float* b2       = (const float*)d_in[8];
    const float* Wc       = (const float*)d_in[9];
    const float* bc       = (const float*)d_in[10];

    int N = in_sizes[0] / D;
    int E = in_sizes[1];

    int *cnt, *cursor, *rowstart, *csrsrc, *bsum;
    float *wfs, *wfn, *bf, *zbuf;
    __half *feat16, *agg16, *w16;
    cudaGetSymbolAddress((void**)&cnt, g_cnt);
    cudaGetSymbolAddress((void**)&cursor, g_cursor);
    cudaGetSymbolAddress((void**)&rowstart, g_rowstart);
    cudaGetSymbolAddress((void**)&csrsrc, g_csrsrc);
    cudaGetSymbolAddress((void**)&bsum, g_bsum);
    cudaGetSymbolAddress((void**)&wfs, g_wfs);
    cudaGetSymbolAddress((void**)&wfn, g_wfn);
    cudaGetSymbolAddress((void**)&bf, g_bf);
    cudaGetSymbolAddress((void**)&zbuf, g_z);
    cudaGetSymbolAddress((void**)&feat16, g_feat16);
    cudaGetSymbolAddress((void**)&agg16, g_agg16);
    cudaGetSymbolAddress((void**)&w16, g_w16);

    static cudaStream_t s1 = nullptr;
    static cudaEvent_t ev0 = nullptr, ev1 = nullptr;
    static int init_done = 0;
    if (!init_done) {
        cudaFuncSetAttribute(gemm_sage_f16,
                             cudaFuncAttributeMaxDynamicSharedMemorySize, 65536);
        if (cudaStreamCreateWithFlags(&s1, cudaStreamNonBlocking) != cudaSuccess) s1 = nullptr;
        if (s1) {
            cudaEventCreateWithFlags(&ev0, cudaEventDisableTiming);
            cudaEventCreateWithFlags(&ev1, cudaEventDisableTiming);
        }
        init_done = 1;
    }

    int mblocks = (N + 127) / 128;
    int gblocks = (N + 7) / 8;
    int n4 = N * (D / 4);
    int nb = (N + SCAN_B - 1) / SCAN_B;
    const int SMEM = 65536;

    // side stream: conversions + fused layer-2 weights (no CSR deps)
    cudaStream_t cs = s1 ? s1 : (cudaStream_t)0;
    if (s1) {
        cudaEventRecord(ev0, 0);
        cudaStreamWaitEvent(s1, ev0, 0);
    }
    conv16_kernel<<<(n4 + 255) / 256, 256, 0, cs>>>(features, feat16, n4);
    wconv_kernel<<<(2 * D * D + 255) / 256, 256, 0, cs>>>(W1s, W1n);
    wfuse_kernel<<<1, 512, 0, cs>>>(W2s, W2n, Wc, b2, bc);
    if (s1) cudaEventRecord(ev1, s1);

    // main stream: CSR build
    cudaMemsetAsync(cnt, 0, (size_t)N * sizeof(int));
    hist_kernel<<<(E / 2 + 255) / 256, 256>>>((const int2*)dst, cnt, E / 2);
    scan_bsum_kernel<<<nb, SCAN_B>>>(cnt, bsum, N);
    scan_fin_kernel<<<nb, SCAN_B>>>(cnt, bsum, rowstart, cursor, N, nb);
    fill2_kernel<<<(E / 2 + 255) / 256, 256>>>((const int2*)src, (const int2*)dst,
                                               cursor, csrsrc, E / 2);

    if (s1) cudaStreamWaitEvent((cudaStream_t)0, ev1, 0);  // join conversions

    gather16_kernel<<<gblocks, 256>>>(feat16, rowstart, csrsrc, agg16, N);
    gemm_sage_f16<<<mblocks, 256, SMEM>>>(feat16, agg16, w16, w16 + D * D,
                                          b1, N, wfs, wfn, zbuf);
    final_kernel<<<(N + 255) / 256, 256>>>(zbuf, rowstart, csrsrc, bf,
                                           (float*)d_out, N);
}